// round 3
// baseline (speedup 1.0000x reference)
#include <cuda_runtime.h>
#include <math.h>

// Problem constants
#define CC    512      // channels
#define O3    1536     // 3*C
#define NN    1024     // H*W
#define BB    8        // batch
#define DIM   64       // head dim
#define HEADS 8

// ---------------------------------------------------------------------------
// Scratch (no allocation allowed -> __device__ globals)
// ---------------------------------------------------------------------------
__device__ float g_scale[O3];                       // proj_g / ||proj_v||
__device__ float g_qkv[(size_t)BB * O3 * NN];       // 50.3 MB qkv buffer

// ---------------------------------------------------------------------------
// Kernel 1: per-row weight-norm scale  s[o] = proj_g[o] / ||proj_v[o,:]||
// one warp per row
// ---------------------------------------------------------------------------
__global__ void scale_kernel(const float* __restrict__ pv,
                             const float* __restrict__ pg) {
    int o = blockIdx.x * 8 + (threadIdx.x >> 5);
    int lane = threadIdx.x & 31;
    const float* row = pv + (size_t)o * CC;
    float s = 0.f;
    #pragma unroll 4
    for (int i = lane; i < CC; i += 32) { float v = row[i]; s += v * v; }
    #pragma unroll
    for (int off = 16; off; off >>= 1) s += __shfl_xor_sync(0xffffffffu, s, off);
    if (lane == 0) g_scale[o] = pg[o] / sqrtf(s);
}

// ---------------------------------------------------------------------------
// Kernel 2: qkv[b,o,n] = sum_c (s[o]*proj_v[o,c]) * x[b,c,n] + proj_b[o]
// Tiled SGEMM: 128x64 block tile, k-tile 16, 256 threads, 8x4 microtile.
// ---------------------------------------------------------------------------
#define PBM 128
#define PBN 64
#define PBK 16

__global__ __launch_bounds__(256)
void proj_gemm(const float* __restrict__ x,
               const float* __restrict__ pv,
               const float* __restrict__ pb) {
    __shared__ float As[PBK * 132];   // [kk][m], stride 132 (pad)
    __shared__ float Bs[PBK * 68];    // [kk][n], stride 68  (pad)

    const int b  = blockIdx.z;
    const int bm = blockIdx.y * PBM;
    const int bn = blockIdx.x * PBN;
    const float* xb = x + (size_t)b * CC * NN;
    float* outp = g_qkv + (size_t)b * O3 * NN;

    const int t  = threadIdx.x;
    const int tx = t & 15;            // n-threads (4 cols each)
    const int ty = t >> 4;            // m-threads (8 rows each)

    float acc[8][4];
    #pragma unroll
    for (int i = 0; i < 8; i++)
        #pragma unroll
        for (int j = 0; j < 4; j++) acc[i][j] = 0.f;

    for (int k0 = 0; k0 < CC; k0 += PBK) {
        // A tile: 128 rows x 16 cols, scaled by g_scale, stored k-major
        #pragma unroll
        for (int i = 0; i < 2; i++) {
            int idx = t + i * 256;          // 512 float4 total
            int r = idx >> 2, c4 = idx & 3;
            float4 v = *(const float4*)(pv + (size_t)(bm + r) * CC + k0 + c4 * 4);
            float sc = g_scale[bm + r];
            As[(c4 * 4 + 0) * 132 + r] = v.x * sc;
            As[(c4 * 4 + 1) * 132 + r] = v.y * sc;
            As[(c4 * 4 + 2) * 132 + r] = v.z * sc;
            As[(c4 * 4 + 3) * 132 + r] = v.w * sc;
        }
        // B tile: 16 rows x 64 cols
        {
            int r = t >> 4, c4 = t & 15;
            float4 v = *(const float4*)(xb + (size_t)(k0 + r) * NN + bn + c4 * 4);
            *(float4*)(Bs + r * 68 + c4 * 4) = v;
        }
        __syncthreads();

        #pragma unroll
        for (int kk = 0; kk < PBK; kk++) {
            float4 a0 = *(const float4*)(As + kk * 132 + ty * 8);
            float4 a1 = *(const float4*)(As + kk * 132 + ty * 8 + 4);
            float4 b0 = *(const float4*)(Bs + kk * 68 + tx * 4);
            float a[8] = {a0.x, a0.y, a0.z, a0.w, a1.x, a1.y, a1.z, a1.w};
            float bv[4] = {b0.x, b0.y, b0.z, b0.w};
            #pragma unroll
            for (int i = 0; i < 8; i++)
                #pragma unroll
                for (int j = 0; j < 4; j++)
                    acc[i][j] += a[i] * bv[j];
        }
        __syncthreads();
    }

    #pragma unroll
    for (int i = 0; i < 8; i++) {
        int o = bm + ty * 8 + i;
        float bias = pb[o];
        float4 v = make_float4(acc[i][0] + bias, acc[i][1] + bias,
                               acc[i][2] + bias, acc[i][3] + bias);
        *(float4*)(outp + (size_t)o * NN + bn + tx * 4) = v;
    }
}

// ---------------------------------------------------------------------------
// Kernel 3: flash attention, CTA = (b, h, 128-query tile)
//   S = scale * Q^T K (tile in SMEM, stored k-major/"transposed"),
//   online softmax over columns, O += P V^T, residual add at the end.
// SMEM (floats):
//   Qs [64][132]  k(=d)-major Q tile
//   Ks [64][132]  k(=d)-major K tile
//   Vt [128][68]  V transposed: [k][d]
//   St [128][132] S/P transposed: [k][q]
//   rowf[128]     softmax rescale factor / final 1/l broadcast
// ---------------------------------------------------------------------------
#define QT 128
#define KT 128
#define OFF_Q 0
#define OFF_K 8448
#define OFF_V 16896
#define OFF_S 25600
#define OFF_F 42496
#define SMEM_FLOATS 42624   // 170,496 bytes

__global__ __launch_bounds__(256, 1)
void attn_kernel(const float* __restrict__ x, float* __restrict__ out) {
    extern __shared__ float sm[];
    float* Qs   = sm + OFF_Q;
    float* Ks   = sm + OFF_K;
    float* Vt   = sm + OFF_V;
    float* St   = sm + OFF_S;
    float* rowf = sm + OFF_F;

    const int t  = threadIdx.x;
    const int bh = blockIdx.y;
    const int b  = bh >> 3, h = bh & 7;
    const int q0 = blockIdx.x * QT;

    const float* Qg = g_qkv + ((size_t)b * O3 + h * DIM) * NN;
    const float* Kg = Qg + (size_t)CC * NN;
    const float* Vg = Qg + (size_t)2 * CC * NN;

    // Load Q tile: 64 d-rows x 128 q-cols
    #pragma unroll
    for (int i = 0; i < 8; i++) {
        int idx = t + i * 256;          // 2048 float4
        int d = idx >> 5, c4 = idx & 31;
        float4 v = *(const float4*)(Qg + (size_t)d * NN + q0 + c4 * 4);
        *(float4*)(Qs + d * 132 + c4 * 4) = v;
    }

    const int tq = t >> 4;   // 0..15: owns q rows tq*8..tq*8+7
    const int tk = t & 15;   // 0..15: GEMM1 k-lanes (interleaved), GEMM2 d-lanes

    float Oacc[8][4];
    #pragma unroll
    for (int i = 0; i < 8; i++)
        #pragma unroll
        for (int j = 0; j < 4; j++) Oacc[i][j] = 0.f;
    float m_run = -3.0e38f, l_run = 0.f;

    for (int k0 = 0; k0 < NN; k0 += KT) {
        __syncthreads();   // protect Ks/Vt/St from previous iteration readers

        // K tile (same layout as Q)
        #pragma unroll
        for (int i = 0; i < 8; i++) {
            int idx = t + i * 256;
            int d = idx >> 5, c4 = idx & 31;
            float4 v = *(const float4*)(Kg + (size_t)d * NN + k0 + c4 * 4);
            *(float4*)(Ks + d * 132 + c4 * 4) = v;
        }
        // V tile transposed: each thread gathers 4 d's at one k, stores float4
        #pragma unroll
        for (int i = 0; i < 8; i++) {
            int idx = t + i * 256;
            int k = idx & 127, d4 = idx >> 7;
            float4 v;
            v.x = Vg[(size_t)(d4 * 4 + 0) * NN + k0 + k];
            v.y = Vg[(size_t)(d4 * 4 + 1) * NN + k0 + k];
            v.z = Vg[(size_t)(d4 * 4 + 2) * NN + k0 + k];
            v.w = Vg[(size_t)(d4 * 4 + 3) * NN + k0 + k];
            *(float4*)(Vt + k * 68 + d4 * 4) = v;
        }
        __syncthreads();

        // GEMM1: St[k][q] = 0.125 * sum_d Qs[d][q] * Ks[d][k]
        // thread micro: 8 q (blocked) x 8 k (interleaved: k = tk + 16*j)
        {
            float s_[8][8];
            #pragma unroll
            for (int i = 0; i < 8; i++)
                #pragma unroll
                for (int j = 0; j < 8; j++) s_[i][j] = 0.f;

            #pragma unroll 4
            for (int d = 0; d < DIM; d++) {
                float4 a0 = *(const float4*)(Qs + d * 132 + tq * 8);
                float4 a1 = *(const float4*)(Qs + d * 132 + tq * 8 + 4);
                float a[8] = {a0.x, a0.y, a0.z, a0.w, a1.x, a1.y, a1.z, a1.w};
                float bv[8];
                #pragma unroll
                for (int j = 0; j < 8; j++) bv[j] = Ks[d * 132 + tk + 16 * j];
                #pragma unroll
                for (int i = 0; i < 8; i++)
                    #pragma unroll
                    for (int j = 0; j < 8; j++)
                        s_[i][j] += a[i] * bv[j];
            }
            #pragma unroll
            for (int j = 0; j < 8; j++) {
                int krow = tk + 16 * j;
                float4 v0 = make_float4(s_[0][j] * 0.125f, s_[1][j] * 0.125f,
                                        s_[2][j] * 0.125f, s_[3][j] * 0.125f);
                float4 v1 = make_float4(s_[4][j] * 0.125f, s_[5][j] * 0.125f,
                                        s_[6][j] * 0.125f, s_[7][j] * 0.125f);
                *(float4*)(St + krow * 132 + tq * 8)     = v0;
                *(float4*)(St + krow * 132 + tq * 8 + 4) = v1;
            }
        }
        __syncthreads();

        // Online softmax: thread t (<128) owns query column q = t of St
        if (t < QT) {
            float tmax = -3.0e38f;
            #pragma unroll 4
            for (int k = 0; k < KT; k++) tmax = fmaxf(tmax, St[k * 132 + t]);
            float newm = fmaxf(m_run, tmax);
            float f = __expf(m_run - newm);
            float ssum = 0.f;
            #pragma unroll 4
            for (int k = 0; k < KT; k++) {
                float p = __expf(St[k * 132 + t] - newm);
                St[k * 132 + t] = p;
                ssum += p;
            }
            l_run = l_run * f + ssum;
            m_run = newm;
            rowf[t] = f;
        }
        __syncthreads();

        // Rescale O, then GEMM2: Oacc[q][d] += sum_k St[k][q] * Vt[k][d]
        {
            float f_[8];
            #pragma unroll
            for (int i = 0; i < 8; i++) f_[i] = rowf[tq * 8 + i];
            #pragma unroll
            for (int i = 0; i < 8; i++)
                #pragma unroll
                for (int j = 0; j < 4; j++) Oacc[i][j] *= f_[i];

            #pragma unroll 4
            for (int kk = 0; kk < KT; kk++) {
                float4 a0 = *(const float4*)(St + kk * 132 + tq * 8);
                float4 a1 = *(const float4*)(St + kk * 132 + tq * 8 + 4);
                float4 b0 = *(const float4*)(Vt + kk * 68 + tk * 4);
                float a[8] = {a0.x, a0.y, a0.z, a0.w, a1.x, a1.y, a1.z, a1.w};
                float bv[4] = {b0.x, b0.y, b0.z, b0.w};
                #pragma unroll
                for (int i = 0; i < 8; i++)
                    #pragma unroll
                    for (int j = 0; j < 4; j++)
                        Oacc[i][j] += a[i] * bv[j];
            }
        }
    }

    __syncthreads();
    if (t < QT) rowf[t] = 1.f / l_run;
    __syncthreads();

    // Epilogue: out[b, h*64+d, q0+q] = x[...] + O[q][d] / l
    const size_t obase = ((size_t)b * CC + h * DIM) * NN + q0;
    #pragma unroll
    for (int i = 0; i < 8; i++) {
        int q = tq * 8 + i;
        float inv = rowf[q];
        #pragma unroll
        for (int j = 0; j < 4; j++) {
            int d = tk * 4 + j;
            size_t addr = obase + (size_t)d * NN + q;
            out[addr] = x[addr] + Oacc[i][j] * inv;
        }
    }
}

// ---------------------------------------------------------------------------
// Launch
// ---------------------------------------------------------------------------
extern "C" void kernel_launch(void* const* d_in, const int* in_sizes, int n_in,
                              void* d_out, int out_size) {
    const float* x  = (const float*)d_in[0];
    const float* pv = (const float*)d_in[1];
    const float* pg = (const float*)d_in[2];
    const float* pb = (const float*)d_in[3];
    float* out = (float*)d_out;

    scale_kernel<<<O3 / 8, 256>>>(pv, pg);

    dim3 pgrid(NN / PBN, O3 / PBM, BB);
    proj_gemm<<<pgrid, 256>>>(x, pv, pb);

    cudaFuncSetAttribute(attn_kernel,
                         cudaFuncAttributeMaxDynamicSharedMemorySize,
                         SMEM_FLOATS * 4);
    dim3 agrid(NN / QT, BB * HEADS);
    attn_kernel<<<agrid, 256, SMEM_FLOATS * 4>>>(x, out);
}

// round 6
// speedup vs baseline: 2.7745x; 2.7745x over previous
#include <cuda_runtime.h>
#include <math.h>

// Problem constants
#define CC    512      // channels
#define O3    1536     // 3*C
#define NN    1024     // H*W
#define BB    8        // batch
#define DIM   64       // head dim
#define HEADS 8

// ---------------------------------------------------------------------------
// Scratch (no allocation allowed -> __device__ globals)
// ---------------------------------------------------------------------------
__device__ float g_w[(size_t)O3 * CC];              // tf32-rounded scaled weights
__device__ float g_qkv[(size_t)BB * O3 * NN];       // 50.3 MB qkv buffer

// ---------------------------------------------------------------------------
// tf32 helpers
// ---------------------------------------------------------------------------
__device__ __forceinline__ float tf32f(float f) {
    unsigned u;
    asm("cvt.rna.tf32.f32 %0, %1;" : "=r"(u) : "f"(f));
    return __uint_as_float(u);
}

__device__ __forceinline__ void mma8(float* c, const unsigned* a, const unsigned* b) {
    asm volatile(
        "mma.sync.aligned.m16n8k8.row.col.f32.tf32.tf32.f32 "
        "{%0,%1,%2,%3}, {%4,%5,%6,%7}, {%8,%9}, {%0,%1,%2,%3};\n"
        : "+f"(c[0]), "+f"(c[1]), "+f"(c[2]), "+f"(c[3])
        : "r"(a[0]), "r"(a[1]), "r"(a[2]), "r"(a[3]), "r"(b[0]), "r"(b[1]));
}

// ---------------------------------------------------------------------------
// Kernel 1: w[o][c] = tf32( proj_g[o]/||proj_v[o,:]|| * proj_v[o][c] )
// one warp per row
// ---------------------------------------------------------------------------
__global__ void prep_w(const float* __restrict__ pv,
                       const float* __restrict__ pg) {
    int o = blockIdx.x * 8 + (threadIdx.x >> 5);
    int lane = threadIdx.x & 31;
    const float* row = pv + (size_t)o * CC;
    float s = 0.f;
    #pragma unroll 4
    for (int i = lane; i < CC; i += 32) { float v = row[i]; s += v * v; }
    #pragma unroll
    for (int off = 16; off; off >>= 1) s += __shfl_xor_sync(0xffffffffu, s, off);
    float sc = pg[o] / sqrtf(s);
    #pragma unroll 4
    for (int i = lane; i < CC; i += 32)
        g_w[(size_t)o * CC + i] = tf32f(row[i] * sc);
}

// ---------------------------------------------------------------------------
// Kernel 2: qkv = w @ x + b  (tf32 mma). CTA tile 128x128, k-tile 32,
// 8 warps in 2(m) x 4(n) grid, warp tile 64x32, m16n8k8 fragments.
// ---------------------------------------------------------------------------
#define PK 32
#define WS_STR 36      // Ws [128 m][32 k]  (A row-major) : a-frag banks 4g+t -> CF
#define XS_STR 136     // Xs [32 k][128 n]  (B k-major)   : b-frag banks 8t+g -> CF

__global__ __launch_bounds__(256)
void proj_mma(const float* __restrict__ x,
              const float* __restrict__ pb) {
    __shared__ float Ws[128 * WS_STR];
    __shared__ float Xs[PK * XS_STR];

    const int b  = blockIdx.z;
    const int bm = blockIdx.y * 128;
    const int bn = blockIdx.x * 128;
    const float* xb = x + (size_t)b * CC * NN;
    float* outp = g_qkv + (size_t)b * O3 * NN;

    const int t    = threadIdx.x;
    const int w    = t >> 5;
    const int lane = t & 31;
    const int g    = lane >> 2;   // groupID
    const int t4   = lane & 3;    // threadID_in_group
    const int moff = (w & 1) * 64;
    const int noff = (w >> 1) * 32;

    float c[4][4][4];
    #pragma unroll
    for (int mf = 0; mf < 4; mf++)
        #pragma unroll
        for (int nf = 0; nf < 4; nf++)
            #pragma unroll
            for (int i = 0; i < 4; i++) c[mf][nf][i] = 0.f;

    for (int k0 = 0; k0 < CC; k0 += PK) {
        // A tile: 128 rows x 32 cols (already tf32)
        #pragma unroll
        for (int i = 0; i < 4; i++) {
            int idx = t + i * 256;
            int r = idx >> 3, k4 = idx & 7;
            float4 v = *(const float4*)(g_w + (size_t)(bm + r) * CC + k0 + k4 * 4);
            *(float4*)(Ws + r * WS_STR + k4 * 4) = v;
        }
        // B tile: 32 rows x 128 cols, cvt to tf32
        #pragma unroll
        for (int i = 0; i < 4; i++) {
            int idx = t + i * 256;
            int r = idx >> 5, n4 = idx & 31;
            float4 v = *(const float4*)(xb + (size_t)(k0 + r) * NN + bn + n4 * 4);
            v.x = tf32f(v.x); v.y = tf32f(v.y); v.z = tf32f(v.z); v.w = tf32f(v.w);
            *(float4*)(Xs + r * XS_STR + n4 * 4) = v;
        }
        __syncthreads();

        #pragma unroll
        for (int ks = 0; ks < 4; ks++) {
            const int koff = ks * 8;
            unsigned a[4][4], bf[4][2];
            #pragma unroll
            for (int mf = 0; mf < 4; mf++) {
                int mb = moff + mf * 16;
                a[mf][0] = __float_as_uint(Ws[(mb + g)     * WS_STR + koff + t4]);
                a[mf][1] = __float_as_uint(Ws[(mb + g + 8) * WS_STR + koff + t4]);
                a[mf][2] = __float_as_uint(Ws[(mb + g)     * WS_STR + koff + t4 + 4]);
                a[mf][3] = __float_as_uint(Ws[(mb + g + 8) * WS_STR + koff + t4 + 4]);
            }
            #pragma unroll
            for (int nf = 0; nf < 4; nf++) {
                int col = noff + nf * 8 + g;
                bf[nf][0] = __float_as_uint(Xs[(koff + t4)     * XS_STR + col]);
                bf[nf][1] = __float_as_uint(Xs[(koff + t4 + 4) * XS_STR + col]);
            }
            #pragma unroll
            for (int mf = 0; mf < 4; mf++)
                #pragma unroll
                for (int nf = 0; nf < 4; nf++)
                    mma8(c[mf][nf], a[mf], bf[nf]);
        }
        __syncthreads();
    }

    // Epilogue: bias + store (float2 per c0/c1 pair)
    #pragma unroll
    for (int mf = 0; mf < 4; mf++) {
        int o = bm + moff + mf * 16 + g;
        float bias0 = pb[o], bias1 = pb[o + 8];
        #pragma unroll
        for (int nf = 0; nf < 4; nf++) {
            int n = bn + noff + nf * 8 + 2 * t4;
            *(float2*)(outp + (size_t)o * NN + n) =
                make_float2(c[mf][nf][0] + bias0, c[mf][nf][1] + bias0);
            *(float2*)(outp + (size_t)(o + 8) * NN + n) =
                make_float2(c[mf][nf][2] + bias1, c[mf][nf][3] + bias1);
        }
    }
}

// ---------------------------------------------------------------------------
// Kernel 3: flash attention with tf32 mma. CTA = (b,h,128-q tile).
// GEMM1: S = (Q/8)^T K  (128q x 128k, K=64d), 8 warps 2m x 4n (64x32 tiles)
// GEMM2: O += P V^T     (128q x 64d,  K=128k), 8 warps 2m x 4n (64x16 tiles)
// SMEM strides chosen so every fragment load is bank-conflict-free.
// ---------------------------------------------------------------------------
#define SQ_STR 136     // Qs/Ks [64 d][128 q|k] : frag banks 8t+g -> CF
#define SV_STR 132     // Vs    [64 d][128 k]   : frag banks 4g+t -> CF
#define SS_STR 164     // St    [128 q][128 k]  : GEMM2 a-frag banks 4g+t -> CF

#define OFF_Q 0
#define OFF_K 8704     // 64*136
#define OFF_V 17408
#define OFF_S 25856    // + 64*132
#define OFF_F 46848    // + 128*164
#define SMEM_FLOATS 46976   // 187,904 bytes

__global__ __launch_bounds__(256, 1)
void attn_mma(const float* __restrict__ x, float* __restrict__ out) {
    extern __shared__ float sm[];
    float* Qs   = sm + OFF_Q;
    float* Ks   = sm + OFF_K;
    float* Vs   = sm + OFF_V;
    float* St   = sm + OFF_S;
    float* rowf = sm + OFF_F;

    const int t    = threadIdx.x;
    const int w    = t >> 5;
    const int lane = t & 31;
    const int g    = lane >> 2;
    const int t4   = lane & 3;
    const int bh   = blockIdx.y;
    const int b    = bh >> 3, h = bh & 7;
    const int q0   = blockIdx.x * 128;

    const float* Qg = g_qkv + ((size_t)b * O3 + h * DIM) * NN;
    const float* Kg = Qg + (size_t)CC * NN;
    const float* Vg = Qg + (size_t)2 * CC * NN;

    // Q tile: [d][q], scaled by 1/8, tf32
    #pragma unroll
    for (int i = 0; i < 8; i++) {
        int idx = t + i * 256;
        int d = idx >> 5, q4 = idx & 31;
        float4 v = *(const float4*)(Qg + (size_t)d * NN + q0 + q4 * 4);
        v.x = tf32f(v.x * 0.125f); v.y = tf32f(v.y * 0.125f);
        v.z = tf32f(v.z * 0.125f); v.w = tf32f(v.w * 0.125f);
        *(float4*)(Qs + d * SQ_STR + q4 * 4) = v;
    }

    const int m1off = (w & 1) * 64, n1off = (w >> 1) * 32;   // GEMM1 warp tile
    const int m2off = (w & 1) * 64, n2off = (w >> 1) * 16;   // GEMM2 warp tile

    float Oa[4][2][4];
    #pragma unroll
    for (int mf = 0; mf < 4; mf++)
        #pragma unroll
        for (int nf = 0; nf < 2; nf++)
            #pragma unroll
            for (int i = 0; i < 4; i++) Oa[mf][nf][i] = 0.f;

    float m_run = -3.0e38f, l_run = 0.f;
    const int sq = t >> 1, half = t & 1;        // softmax: 2 threads per q row
    float* srow = St + sq * SS_STR + half * 64;

    for (int k0 = 0; k0 < NN; k0 += 128) {
        __syncthreads();   // protect Ks/Vs/St/rowf from previous iteration

        // K and V tiles: [d][k], tf32
        #pragma unroll
        for (int i = 0; i < 8; i++) {
            int idx = t + i * 256;
            int d = idx >> 5, k4 = idx & 31;
            float4 v = *(const float4*)(Kg + (size_t)d * NN + k0 + k4 * 4);
            v.x = tf32f(v.x); v.y = tf32f(v.y); v.z = tf32f(v.z); v.w = tf32f(v.w);
            *(float4*)(Ks + d * SQ_STR + k4 * 4) = v;
            float4 u = *(const float4*)(Vg + (size_t)d * NN + k0 + k4 * 4);
            u.x = tf32f(u.x); u.y = tf32f(u.y); u.z = tf32f(u.z); u.w = tf32f(u.w);
            *(float4*)(Vs + d * SV_STR + k4 * 4) = u;
        }
        __syncthreads();

        // ---- GEMM1: St[q][k] = Q^T K ----
        {
            float c1[4][4][4];
            #pragma unroll
            for (int mf = 0; mf < 4; mf++)
                #pragma unroll
                for (int nf = 0; nf < 4; nf++)
                    #pragma unroll
                    for (int i = 0; i < 4; i++) c1[mf][nf][i] = 0.f;

            #pragma unroll
            for (int ks = 0; ks < 8; ks++) {
                const int koff = ks * 8;
                unsigned a[4][4], bf[4][2];
                #pragma unroll
                for (int mf = 0; mf < 4; mf++) {
                    int q = m1off + mf * 16 + g;
                    a[mf][0] = __float_as_uint(Qs[(koff + t4)     * SQ_STR + q]);
                    a[mf][1] = __float_as_uint(Qs[(koff + t4)     * SQ_STR + q + 8]);
                    a[mf][2] = __float_as_uint(Qs[(koff + t4 + 4) * SQ_STR + q]);
                    a[mf][3] = __float_as_uint(Qs[(koff + t4 + 4) * SQ_STR + q + 8]);
                }
                #pragma unroll
                for (int nf = 0; nf < 4; nf++) {
                    int col = n1off + nf * 8 + g;
                    bf[nf][0] = __float_as_uint(Ks[(koff + t4)     * SQ_STR + col]);
                    bf[nf][1] = __float_as_uint(Ks[(koff + t4 + 4) * SQ_STR + col]);
                }
                #pragma unroll
                for (int mf = 0; mf < 4; mf++)
                    #pragma unroll
                    for (int nf = 0; nf < 4; nf++)
                        mma8(c1[mf][nf], a[mf], bf[nf]);
            }
            // store S tile (fp32)
            #pragma unroll
            for (int mf = 0; mf < 4; mf++) {
                int q = m1off + mf * 16 + g;
                #pragma unroll
                for (int nf = 0; nf < 4; nf++) {
                    int kc = n1off + nf * 8 + 2 * t4;
                    *(float2*)(St + q * SS_STR + kc) =
                        make_float2(c1[mf][nf][0], c1[mf][nf][1]);
                    *(float2*)(St + (q + 8) * SS_STR + kc) =
                        make_float2(c1[mf][nf][2], c1[mf][nf][3]);
                }
            }
        }
        __syncthreads();

        // ---- online softmax: pair (2 threads) per q row, 64 cols each ----
        {
            float tmax = -3.0e38f;
            #pragma unroll
            for (int j = 0; j < 16; j++) {
                float4 v = *(const float4*)(srow + j * 4);
                tmax = fmaxf(tmax, fmaxf(fmaxf(v.x, v.y), fmaxf(v.z, v.w)));
            }
            tmax = fmaxf(tmax, __shfl_xor_sync(0xffffffffu, tmax, 1));
            float newm = fmaxf(m_run, tmax);
            float fsc  = __expf(m_run - newm);
            float ssum = 0.f;
            #pragma unroll
            for (int j = 0; j < 16; j++) {
                float4 v = *(const float4*)(srow + j * 4);
                float p0 = __expf(v.x - newm), p1 = __expf(v.y - newm);
                float p2 = __expf(v.z - newm), p3 = __expf(v.w - newm);
                ssum += (p0 + p1) + (p2 + p3);
                v.x = tf32f(p0); v.y = tf32f(p1); v.z = tf32f(p2); v.w = tf32f(p3);
                *(float4*)(srow + j * 4) = v;
            }
            ssum += __shfl_xor_sync(0xffffffffu, ssum, 1);
            l_run = l_run * fsc + ssum;
            m_run = newm;
            if (half == 0) rowf[sq] = fsc;
        }
        __syncthreads();

        // ---- rescale O, then GEMM2: O[q][d] += P V^T ----
        #pragma unroll
        for (int mf = 0; mf < 4; mf++) {
            float f0 = rowf[m2off + mf * 16 + g];
            float f1 = rowf[m2off + mf * 16 + g + 8];
            #pragma unroll
            for (int nf = 0; nf < 2; nf++) {
                Oa[mf][nf][0] *= f0; Oa[mf][nf][1] *= f0;
                Oa[mf][nf][2] *= f1; Oa[mf][nf][3] *= f1;
            }
        }
        #pragma unroll
        for (int ks = 0; ks < 16; ks++) {
            const int koff = ks * 8;
            unsigned a[4][4], bf[2][2];
            #pragma unroll
            for (int mf = 0; mf < 4; mf++) {
                int mb = m2off + mf * 16;
                a[mf][0] = __float_as_uint(St[(mb + g)     * SS_STR + koff + t4]);
                a[mf][1] = __float_as_uint(St[(mb + g + 8) * SS_STR + koff + t4]);
                a[mf][2] = __float_as_uint(St[(mb + g)     * SS_STR + koff + t4 + 4]);
                a[mf][3] = __float_as_uint(St[(mb + g + 8) * SS_STR + koff + t4 + 4]);
            }
            #pragma unroll
            for (int nf = 0; nf < 2; nf++) {
                int dd = n2off + nf * 8 + g;
                bf[nf][0] = __float_as_uint(Vs[dd * SV_STR + koff + t4]);
                bf[nf][1] = __float_as_uint(Vs[dd * SV_STR + koff + t4 + 4]);
            }
            #pragma unroll
            for (int mf = 0; mf < 4; mf++)
                #pragma unroll
                for (int nf = 0; nf < 2; nf++)
                    mma8(Oa[mf][nf], a[mf], bf[nf]);
        }
    }

    __syncthreads();
    if (half == 0) rowf[sq] = 1.f / l_run;
    __syncthreads();

    // Epilogue: out[b, h*64+d, q0+q] = x + O/l
    const size_t base = ((size_t)b * CC + h * DIM) * NN + q0;
    #pragma unroll
    for (int mf = 0; mf < 4; mf++) {
        int q = m2off + mf * 16 + g;
        float inv0 = rowf[q], inv1 = rowf[q + 8];
        #pragma unroll
        for (int nf = 0; nf < 2; nf++) {
            int d = n2off + nf * 8 + 2 * t4;
            size_t a0 = base + (size_t)d * NN + q;
            out[a0]      = x[a0]      + Oa[mf][nf][0] * inv0;
            out[a0 + NN] = x[a0 + NN] + Oa[mf][nf][1] * inv0;
            size_t a2 = a0 + 8;
            out[a2]      = x[a2]      + Oa[mf][nf][2] * inv1;
            out[a2 + NN] = x[a2 + NN] + Oa[mf][nf][3] * inv1;
        }
    }
}

// ---------------------------------------------------------------------------
// Launch
// ---------------------------------------------------------------------------
extern "C" void kernel_launch(void* const* d_in, const int* in_sizes, int n_in,
                              void* d_out, int out_size) {
    const float* x  = (const float*)d_in[0];
    const float* pv = (const float*)d_in[1];
    const float* pg = (const float*)d_in[2];
    const float* pb = (const float*)d_in[3];
    float* out = (float*)d_out;

    prep_w<<<O3 / 8, 256>>>(pv, pg);

    dim3 pgrid(NN / 128, O3 / 128, BB);
    proj_mma<<<pgrid, 256>>>(x, pb);

    cudaFuncSetAttribute(attn_mma,
                         cudaFuncAttributeMaxDynamicSharedMemorySize,
                         SMEM_FLOATS * 4);
    dim3 agrid(NN / 128, BB * HEADS);
    attn_mma<<<agrid, 256, SMEM_FLOATS * 4>>>(x, out);
}

// round 7
// speedup vs baseline: 4.2835x; 1.5439x over previous
#include <cuda_runtime.h>
#include <cuda_bf16.h>
#include <math.h>

// Problem constants
#define CC    512      // channels
#define O3    1536     // 3*C
#define NN    1024     // H*W
#define BB    8        // batch
#define DIM   64       // head dim
#define HEADS 8

// ---------------------------------------------------------------------------
// Scratch
// ---------------------------------------------------------------------------
__device__ float g_w[(size_t)O3 * CC];              // tf32-rounded scaled weights
__device__ float g_qkv[(size_t)BB * O3 * NN];       // 50.3 MB qkv buffer

// ---------------------------------------------------------------------------
// helpers
// ---------------------------------------------------------------------------
__device__ __forceinline__ float tf32f(float f) {
    unsigned u;
    asm("cvt.rna.tf32.f32 %0, %1;" : "=r"(u) : "f"(f));
    return __uint_as_float(u);
}
__device__ __forceinline__ unsigned smaddr(const void* p) {
    return (unsigned)__cvta_generic_to_shared(p);
}
__device__ __forceinline__ void cpa16(unsigned dst, const void* src) {
    asm volatile("cp.async.cg.shared.global [%0], [%1], 16;" :: "r"(dst), "l"(src));
}
__device__ __forceinline__ void mma8(float* c, const unsigned* a, const unsigned* b) {
    asm volatile(
        "mma.sync.aligned.m16n8k8.row.col.f32.tf32.tf32.f32 "
        "{%0,%1,%2,%3}, {%4,%5,%6,%7}, {%8,%9}, {%0,%1,%2,%3};\n"
        : "+f"(c[0]), "+f"(c[1]), "+f"(c[2]), "+f"(c[3])
        : "r"(a[0]), "r"(a[1]), "r"(a[2]), "r"(a[3]), "r"(b[0]), "r"(b[1]));
}
__device__ __forceinline__ void mma16(float* c, const unsigned* a, const unsigned* b) {
    asm volatile(
        "mma.sync.aligned.m16n8k16.row.col.f32.bf16.bf16.f32 "
        "{%0,%1,%2,%3}, {%4,%5,%6,%7}, {%8,%9}, {%0,%1,%2,%3};\n"
        : "+f"(c[0]), "+f"(c[1]), "+f"(c[2]), "+f"(c[3])
        : "r"(a[0]), "r"(a[1]), "r"(a[2]), "r"(a[3]), "r"(b[0]), "r"(b[1]));
}
__device__ __forceinline__ void ldsm4(unsigned* r, unsigned a) {
    asm volatile("ldmatrix.sync.aligned.m8n8.x4.shared.b16 {%0,%1,%2,%3}, [%4];"
        : "=r"(r[0]), "=r"(r[1]), "=r"(r[2]), "=r"(r[3]) : "r"(a));
}
__device__ __forceinline__ void ldsm4t(unsigned* r, unsigned a) {
    asm volatile("ldmatrix.sync.aligned.m8n8.x4.trans.shared.b16 {%0,%1,%2,%3}, [%4];"
        : "=r"(r[0]), "=r"(r[1]), "=r"(r[2]), "=r"(r[3]) : "r"(a));
}
__device__ __forceinline__ void ldsm2(unsigned* r, unsigned a) {
    asm volatile("ldmatrix.sync.aligned.m8n8.x2.shared.b16 {%0,%1}, [%2];"
        : "=r"(r[0]), "=r"(r[1]) : "r"(a));
}
__device__ __forceinline__ void ldsm2t(unsigned* r, unsigned a) {
    asm volatile("ldmatrix.sync.aligned.m8n8.x2.trans.shared.b16 {%0,%1}, [%2];"
        : "=r"(r[0]), "=r"(r[1]) : "r"(a));
}

// ---------------------------------------------------------------------------
// Kernel 1: w[o][c] = tf32( proj_g[o]/||proj_v[o,:]|| * proj_v[o][c] )
// ---------------------------------------------------------------------------
__global__ void prep_w(const float* __restrict__ pv,
                       const float* __restrict__ pg) {
    int o = blockIdx.x * 8 + (threadIdx.x >> 5);
    int lane = threadIdx.x & 31;
    const float* row = pv + (size_t)o * CC;
    float s = 0.f;
    #pragma unroll 4
    for (int i = lane; i < CC; i += 32) { float v = row[i]; s += v * v; }
    #pragma unroll
    for (int off = 16; off; off >>= 1) s += __shfl_xor_sync(0xffffffffu, s, off);
    float sc = pg[o] / sqrtf(s);
    #pragma unroll 4
    for (int i = lane; i < CC; i += 32)
        g_w[(size_t)o * CC + i] = tf32f(row[i] * sc);
}

// ---------------------------------------------------------------------------
// Kernel 2: qkv = w @ x + b  (tf32 mma, cp.async 2-stage double buffer).
// CTA tile 128x128, k-tile 32, 8 warps 2m x 4n (64x32 warp tiles).
// ---------------------------------------------------------------------------
#define PK 32
#define WS_STR 36      // Ws [128 m][32 k] row-major
#define XS_STR 136     // Xs [32 k][128 n] k-major
#define WS_FLOATS (128 * WS_STR)   // 4608
#define XS_FLOATS (PK * XS_STR)    // 4352
#define PROJ_SMEM ((2 * (WS_FLOATS + XS_FLOATS)) * 4)   // 71680 B

__global__ __launch_bounds__(256, 2)
void proj_mma(const float* __restrict__ x,
              const float* __restrict__ pb) {
    extern __shared__ float psm[];
    float* Ws = psm;                        // [2][WS_FLOATS]
    float* Xs = psm + 2 * WS_FLOATS;        // [2][XS_FLOATS]

    const int b  = blockIdx.z;
    const int bm = blockIdx.y * 128;
    const int bn = blockIdx.x * 128;
    const float* xb = x + (size_t)b * CC * NN;
    float* outp = g_qkv + (size_t)b * O3 * NN;

    const int t    = threadIdx.x;
    const int w    = t >> 5;
    const int lane = t & 31;
    const int g    = lane >> 2;
    const int t4   = lane & 3;
    const int moff = (w & 1) * 64;
    const int noff = (w >> 1) * 32;

    const unsigned ws_u = smaddr(Ws);
    const unsigned xs_u = smaddr(Xs);

    float c[4][4][4];
    #pragma unroll
    for (int mf = 0; mf < 4; mf++)
        #pragma unroll
        for (int nf = 0; nf < 4; nf++)
            #pragma unroll
            for (int i = 0; i < 4; i++) c[mf][nf][i] = 0.f;

    // ---- async tile loader: 1024 float4 each for W and X ----
    auto load_tiles = [&](int buf, int k0) {
        unsigned wdst = ws_u + buf * (WS_FLOATS * 4);
        unsigned xdst = xs_u + buf * (XS_FLOATS * 4);
        #pragma unroll
        for (int i = 0; i < 4; i++) {
            int idx = t + i * 256;
            int r = idx >> 3, k4 = idx & 7;
            cpa16(wdst + (r * WS_STR + k4 * 4) * 4,
                  g_w + (size_t)(bm + r) * CC + k0 + k4 * 4);
        }
        #pragma unroll
        for (int i = 0; i < 4; i++) {
            int idx = t + i * 256;
            int r = idx >> 5, n4 = idx & 31;
            cpa16(xdst + (r * XS_STR + n4 * 4) * 4,
                  xb + (size_t)(k0 + r) * NN + bn + n4 * 4);
        }
    };

    load_tiles(0, 0);
    asm volatile("cp.async.commit_group;");

    for (int kt = 0; kt < 16; kt++) {
        if (kt < 15) load_tiles((kt + 1) & 1, (kt + 1) * PK);
        asm volatile("cp.async.commit_group;");
        asm volatile("cp.async.wait_group 1;");
        __syncthreads();

        const float* Wc = Ws + (kt & 1) * WS_FLOATS;
        const float* Xc = Xs + (kt & 1) * XS_FLOATS;

        #pragma unroll
        for (int ks = 0; ks < 4; ks++) {
            const int koff = ks * 8;
            unsigned a[4][4], bf[4][2];
            #pragma unroll
            for (int mf = 0; mf < 4; mf++) {
                int mb = moff + mf * 16;
                a[mf][0] = __float_as_uint(Wc[(mb + g)     * WS_STR + koff + t4]);
                a[mf][1] = __float_as_uint(Wc[(mb + g + 8) * WS_STR + koff + t4]);
                a[mf][2] = __float_as_uint(Wc[(mb + g)     * WS_STR + koff + t4 + 4]);
                a[mf][3] = __float_as_uint(Wc[(mb + g + 8) * WS_STR + koff + t4 + 4]);
            }
            #pragma unroll
            for (int nf = 0; nf < 4; nf++) {
                int col = noff + nf * 8 + g;
                bf[nf][0] = __float_as_uint(Xc[(koff + t4)     * XS_STR + col]);
                bf[nf][1] = __float_as_uint(Xc[(koff + t4 + 4) * XS_STR + col]);
            }
            #pragma unroll
            for (int mf = 0; mf < 4; mf++)
                #pragma unroll
                for (int nf = 0; nf < 4; nf++)
                    mma8(c[mf][nf], a[mf], bf[nf]);
        }
        __syncthreads();
    }

    #pragma unroll
    for (int mf = 0; mf < 4; mf++) {
        int o = bm + moff + mf * 16 + g;
        float bias0 = pb[o], bias1 = pb[o + 8];
        #pragma unroll
        for (int nf = 0; nf < 4; nf++) {
            int n = bn + noff + nf * 8 + 2 * t4;
            *(float2*)(outp + (size_t)o * NN + n) =
                make_float2(c[mf][nf][0] + bias0, c[mf][nf][1] + bias0);
            *(float2*)(outp + (size_t)(o + 8) * NN + n) =
                make_float2(c[mf][nf][2] + bias1, c[mf][nf][3] + bias1);
        }
    }
}

// ---------------------------------------------------------------------------
// Kernel 3: flash attention, bf16 m16n8k16 mma + ldmatrix.
// CTA = (b,h,128-q tile). Register-resident softmax (no fp32 S round trip).
// SMEM (bf16 stride 136 = 272B = 17 x 16B -> all ldmatrix phases conflict-free)
// ---------------------------------------------------------------------------
#define STR 136
#define QS_OFF   0
#define KS_OFF   17408
#define VS_OFF   34816
#define PB_OFF   52224
#define PMAX_OFF 87040
#define PSUM_OFF 89088
#define ROWM_OFF 91136
#define ROWL_OFF 91648
#define ROWF_OFF 92160
#define ATTN_SMEM 92672

__global__ __launch_bounds__(256, 2)
void attn_mma(const float* __restrict__ x, float* __restrict__ out) {
    extern __shared__ char smc[];
    __nv_bfloat16* Qs = (__nv_bfloat16*)(smc + QS_OFF);
    __nv_bfloat16* Ks = (__nv_bfloat16*)(smc + KS_OFF);
    __nv_bfloat16* Vs = (__nv_bfloat16*)(smc + VS_OFF);
    __nv_bfloat16* Pb = (__nv_bfloat16*)(smc + PB_OFF);
    float* pmax = (float*)(smc + PMAX_OFF);   // [4][128]
    float* psum = (float*)(smc + PSUM_OFF);   // [4][128]
    float* rowm = (float*)(smc + ROWM_OFF);
    float* rowl = (float*)(smc + ROWL_OFF);
    float* rowf = (float*)(smc + ROWF_OFF);

    const int t    = threadIdx.x;
    const int w    = t >> 5;
    const int lane = t & 31;
    const int g    = lane >> 2;
    const int t4   = lane & 3;
    const int bh   = blockIdx.y;
    const int b    = bh >> 3, h = bh & 7;
    const int q0   = blockIdx.x * 128;

    const int half  = w & 1;            // q-half owner
    const int cg    = w >> 1;           // column group
    const int m1off = half * 64;
    const int n1off = cg * 32;
    const int m2off = half * 64;
    const int n2off = cg * 16;

    const float* Qg = g_qkv + ((size_t)b * O3 + h * DIM) * NN;
    const float* Kg = Qg + (size_t)CC * NN;
    const float* Vg = Qg + (size_t)2 * CC * NN;

    const unsigned qs_u = smaddr(Qs), ks_u = smaddr(Ks);
    const unsigned vs_u = smaddr(Vs), pb_u = smaddr(Pb);

    // ldmatrix per-lane address components
    const int rAt = ((lane & 16) >> 1) + (lane & 7);  // trans A: d-row part
    const int cAt = lane & 8;                         // trans A: col part
    const int rBt = (lane & 8) + (lane & 7);          // trans B (x2): d-row part
    const int rA2 = (lane & 8) + (lane & 7);          // normal A: q-row part
    const int cA2 = (lane & 16) >> 1;                 // normal A: col part
    const int rB2 = lane & 7;                         // normal B (x2): d-row part
    const int cB2 = lane & 8;                         // normal B (x2): col part

    // Q tile: [d][q] bf16, scaled by 1/8
    #pragma unroll
    for (int i = 0; i < 8; i++) {
        int idx = t + i * 256;
        int d = idx >> 5, c4 = idx & 31;
        float4 v = *(const float4*)(Qg + (size_t)d * NN + q0 + c4 * 4);
        *(__nv_bfloat162*)(Qs + d * STR + c4 * 4) =
            __floats2bfloat162_rn(v.x * 0.125f, v.y * 0.125f);
        *(__nv_bfloat162*)(Qs + d * STR + c4 * 4 + 2) =
            __floats2bfloat162_rn(v.z * 0.125f, v.w * 0.125f);
    }
    if (t < 128) { rowm[t] = -3.0e38f; rowl[t] = 0.f; }

    float Oa[4][2][4];
    #pragma unroll
    for (int mf = 0; mf < 4; mf++)
        #pragma unroll
        for (int nf = 0; nf < 2; nf++)
            #pragma unroll
            for (int i = 0; i < 4; i++) Oa[mf][nf][i] = 0.f;

    for (int k0 = 0; k0 < NN; k0 += 128) {
        __syncthreads();   // protect Ks/Vs (prev GEMM2) + init

        // K and V tiles: [d][k] bf16
        #pragma unroll
        for (int i = 0; i < 8; i++) {
            int idx = t + i * 256;
            int d = idx >> 5, c4 = idx & 31;
            float4 v = *(const float4*)(Kg + (size_t)d * NN + k0 + c4 * 4);
            *(__nv_bfloat162*)(Ks + d * STR + c4 * 4)     = __floats2bfloat162_rn(v.x, v.y);
            *(__nv_bfloat162*)(Ks + d * STR + c4 * 4 + 2) = __floats2bfloat162_rn(v.z, v.w);
            float4 u = *(const float4*)(Vg + (size_t)d * NN + k0 + c4 * 4);
            *(__nv_bfloat162*)(Vs + d * STR + c4 * 4)     = __floats2bfloat162_rn(u.x, u.y);
            *(__nv_bfloat162*)(Vs + d * STR + c4 * 4 + 2) = __floats2bfloat162_rn(u.z, u.w);
        }
        __syncthreads();

        // ---- GEMM1: S[q][k] = Q^T K  (bf16, d = 4 x k16) ----
        float c1[4][4][4];
        #pragma unroll
        for (int mf = 0; mf < 4; mf++)
            #pragma unroll
            for (int nf = 0; nf < 4; nf++)
                #pragma unroll
                for (int i = 0; i < 4; i++) c1[mf][nf][i] = 0.f;

        #pragma unroll
        for (int ks = 0; ks < 4; ks++) {
            const int koff = ks * 16;
            unsigned a[4][4], bq[4][2];
            #pragma unroll
            for (int mf = 0; mf < 4; mf++)
                ldsm4t(a[mf], qs_u +
                    (unsigned)(((koff + rAt) * STR + m1off + mf * 16 + cAt) * 2));
            #pragma unroll
            for (int nf = 0; nf < 4; nf++)
                ldsm2t(bq[nf], ks_u +
                    (unsigned)(((koff + rBt) * STR + n1off + nf * 8) * 2));
            #pragma unroll
            for (int mf = 0; mf < 4; mf++)
                #pragma unroll
                for (int nf = 0; nf < 4; nf++)
                    mma16(c1[mf][nf], a[mf], bq[nf]);
        }

        // ---- softmax phase 1: per-warp row maxima ----
        #pragma unroll
        for (int mf = 0; mf < 4; mf++) {
            float m0 = -3.0e38f, m1 = -3.0e38f;
            #pragma unroll
            for (int nf = 0; nf < 4; nf++) {
                m0 = fmaxf(m0, fmaxf(c1[mf][nf][0], c1[mf][nf][1]));
                m1 = fmaxf(m1, fmaxf(c1[mf][nf][2], c1[mf][nf][3]));
            }
            m0 = fmaxf(m0, __shfl_xor_sync(0xffffffffu, m0, 1));
            m0 = fmaxf(m0, __shfl_xor_sync(0xffffffffu, m0, 2));
            m1 = fmaxf(m1, __shfl_xor_sync(0xffffffffu, m1, 1));
            m1 = fmaxf(m1, __shfl_xor_sync(0xffffffffu, m1, 2));
            if (t4 == 0) {
                int r = m1off + mf * 16 + g;
                pmax[cg * 128 + r]     = m0;
                pmax[cg * 128 + r + 8] = m1;
            }
        }
        __syncthreads();

        // ---- softmax phase 2: exp in regs, P -> bf16, partial sums ----
        #pragma unroll
        for (int mf = 0; mf < 4; mf++) {
            int r0 = m1off + mf * 16 + g;
            int r1 = r0 + 8;
            float nm0 = fmaxf(fmaxf(fmaxf(pmax[r0], pmax[128 + r0]),
                                    fmaxf(pmax[256 + r0], pmax[384 + r0])), rowm[r0]);
            float nm1 = fmaxf(fmaxf(fmaxf(pmax[r1], pmax[128 + r1]),
                                    fmaxf(pmax[256 + r1], pmax[384 + r1])), rowm[r1]);
            float s0 = 0.f, s1 = 0.f;
            #pragma unroll
            for (int nf = 0; nf < 4; nf++) {
                float p0 = __expf(c1[mf][nf][0] - nm0);
                float p1 = __expf(c1[mf][nf][1] - nm0);
                float p2 = __expf(c1[mf][nf][2] - nm1);
                float p3 = __expf(c1[mf][nf][3] - nm1);
                s0 += p0 + p1; s1 += p2 + p3;
                int col = n1off + nf * 8 + 2 * t4;
                *(__nv_bfloat162*)(Pb + r0 * STR + col) = __floats2bfloat162_rn(p0, p1);
                *(__nv_bfloat162*)(Pb + r1 * STR + col) = __floats2bfloat162_rn(p2, p3);
            }
            s0 += __shfl_xor_sync(0xffffffffu, s0, 1);
            s0 += __shfl_xor_sync(0xffffffffu, s0, 2);
            s1 += __shfl_xor_sync(0xffffffffu, s1, 1);
            s1 += __shfl_xor_sync(0xffffffffu, s1, 2);
            if (t4 == 0) {
                psum[cg * 128 + r0] = s0;
                psum[cg * 128 + r1] = s1;
            }
        }
        __syncthreads();

        // ---- softmax phase 3: update row state (one thread per row) ----
        if (t < 128) {
            float old = rowm[t];
            float nm = fmaxf(fmaxf(fmaxf(pmax[t], pmax[128 + t]),
                                   fmaxf(pmax[256 + t], pmax[384 + t])), old);
            float f = __expf(old - nm);
            rowl[t] = rowl[t] * f +
                      (psum[t] + psum[128 + t] + psum[256 + t] + psum[384 + t]);
            rowm[t] = nm;
            rowf[t] = f;
        }
        __syncthreads();

        // ---- rescale O, then GEMM2: O[q][d] += P V^T (k = 8 x k16) ----
        #pragma unroll
        for (int mf = 0; mf < 4; mf++) {
            float f0 = rowf[m2off + mf * 16 + g];
            float f1 = rowf[m2off + mf * 16 + g + 8];
            #pragma unroll
            for (int nf = 0; nf < 2; nf++) {
                Oa[mf][nf][0] *= f0; Oa[mf][nf][1] *= f0;
                Oa[mf][nf][2] *= f1; Oa[mf][nf][3] *= f1;
            }
        }
        #pragma unroll
        for (int ks = 0; ks < 8; ks++) {
            const int koff = ks * 16;
            unsigned a[4][4], bv[2][2];
            #pragma unroll
            for (int mf = 0; mf < 4; mf++)
                ldsm4(a[mf], pb_u +
                    (unsigned)(((m2off + mf * 16 + rA2) * STR + koff + cA2) * 2));
            #pragma unroll
            for (int nf = 0; nf < 2; nf++)
                ldsm2(bv[nf], vs_u +
                    (unsigned)(((n2off + nf * 8 + rB2) * STR + koff + cB2) * 2));
            #pragma unroll
            for (int mf = 0; mf < 4; mf++)
                #pragma unroll
                for (int nf = 0; nf < 2; nf++)
                    mma16(Oa[mf][nf], a[mf], bv[nf]);
        }
    }

    // Epilogue: out[b, h*64+d, q0+q] = x + O/l
    const size_t base = ((size_t)b * CC + h * DIM) * NN + q0;
    #pragma unroll
    for (int mf = 0; mf < 4; mf++) {
        int q = m2off + mf * 16 + g;
        float inv0 = 1.f / rowl[q];
        float inv1 = 1.f / rowl[q + 8];
        #pragma unroll
        for (int nf = 0; nf < 2; nf++) {
            int d = n2off + nf * 8 + 2 * t4;
            size_t a0 = base + (size_t)d * NN + q;
            out[a0]      = x[a0]      + Oa[mf][nf][0] * inv0;
            out[a0 + NN] = x[a0 + NN] + Oa[mf][nf][1] * inv0;
            size_t a2 = a0 + 8;
            out[a2]      = x[a2]      + Oa[mf][nf][2] * inv1;
            out[a2 + NN] = x[a2 + NN] + Oa[mf][nf][3] * inv1;
        }
    }
}

// ---------------------------------------------------------------------------
// Launch
// ---------------------------------------------------------------------------
extern "C" void kernel_launch(void* const* d_in, const int* in_sizes, int n_in,
                              void* d_out, int out_size) {
    const float* x  = (const float*)d_in[0];
    const float* pv = (const float*)d_in[1];
    const float* pg = (const float*)d_in[2];
    const float* pb = (const float*)d_in[3];
    float* out = (float*)d_out;

    prep_w<<<O3 / 8, 256>>>(pv, pg);

    cudaFuncSetAttribute(proj_mma,
                         cudaFuncAttributeMaxDynamicSharedMemorySize, PROJ_SMEM);
    dim3 pgrid(NN / 128, O3 / 128, BB);
    proj_mma<<<pgrid, 256, PROJ_SMEM>>>(x, pb);

    cudaFuncSetAttribute(attn_mma,
                         cudaFuncAttributeMaxDynamicSharedMemorySize, ATTN_SMEM);
    dim3 agrid(NN / 128, BB * HEADS);
    attn_mma<<<agrid, 256, ATTN_SMEM>>>(x, out);
}

// round 8
// speedup vs baseline: 5.0982x; 1.1902x over previous
#include <cuda_runtime.h>
#include <cuda_fp16.h>
#include <math.h>

// Problem constants
#define CC    512      // channels
#define O3    1536     // 3*C
#define NN    1024     // H*W
#define BB    8        // batch
#define DIM   64       // head dim
#define HEADS 8

// ---------------------------------------------------------------------------
// Scratch
// ---------------------------------------------------------------------------
__device__ float  g_w[(size_t)O3 * CC];               // fragment-swizzled tf32 weights
__device__ __half g_qkvh[(size_t)BB * O3 * NN];       // 25 MB fp16 qkv

// ---------------------------------------------------------------------------
// helpers
// ---------------------------------------------------------------------------
__device__ __forceinline__ float tf32f(float f) {
    unsigned u;
    asm("cvt.rna.tf32.f32 %0, %1;" : "=r"(u) : "f"(f));
    return __uint_as_float(u);
}
__device__ __forceinline__ unsigned smaddr(const void* p) {
    return (unsigned)__cvta_generic_to_shared(p);
}
__device__ __forceinline__ void cpa16(unsigned dst, const void* src) {
    asm volatile("cp.async.cg.shared.global [%0], [%1], 16;" :: "r"(dst), "l"(src));
}
__device__ __forceinline__ void cp_commit() {
    asm volatile("cp.async.commit_group;");
}
template<int N> __device__ __forceinline__ void cp_wait() {
    asm volatile("cp.async.wait_group %0;" :: "n"(N));
}
__device__ __forceinline__ void mma8(float* c, const unsigned* a, const unsigned* b) {
    asm volatile(
        "mma.sync.aligned.m16n8k8.row.col.f32.tf32.tf32.f32 "
        "{%0,%1,%2,%3}, {%4,%5,%6,%7}, {%8,%9}, {%0,%1,%2,%3};\n"
        : "+f"(c[0]), "+f"(c[1]), "+f"(c[2]), "+f"(c[3])
        : "r"(a[0]), "r"(a[1]), "r"(a[2]), "r"(a[3]), "r"(b[0]), "r"(b[1]));
}
__device__ __forceinline__ void mma16h(float* c, const unsigned* a, const unsigned* b) {
    asm volatile(
        "mma.sync.aligned.m16n8k16.row.col.f32.f16.f16.f32 "
        "{%0,%1,%2,%3}, {%4,%5,%6,%7}, {%8,%9}, {%0,%1,%2,%3};\n"
        : "+f"(c[0]), "+f"(c[1]), "+f"(c[2]), "+f"(c[3])
        : "r"(a[0]), "r"(a[1]), "r"(a[2]), "r"(a[3]), "r"(b[0]), "r"(b[1]));
}
__device__ __forceinline__ void ldsm4(unsigned* r, unsigned a) {
    asm volatile("ldmatrix.sync.aligned.m8n8.x4.shared.b16 {%0,%1,%2,%3}, [%4];"
        : "=r"(r[0]), "=r"(r[1]), "=r"(r[2]), "=r"(r[3]) : "r"(a));
}
__device__ __forceinline__ void ldsm4t(unsigned* r, unsigned a) {
    asm volatile("ldmatrix.sync.aligned.m8n8.x4.trans.shared.b16 {%0,%1,%2,%3}, [%4];"
        : "=r"(r[0]), "=r"(r[1]), "=r"(r[2]), "=r"(r[3]) : "r"(a));
}
__device__ __forceinline__ void ldsm2(unsigned* r, unsigned a) {
    asm volatile("ldmatrix.sync.aligned.m8n8.x2.shared.b16 {%0,%1}, [%2];"
        : "=r"(r[0]), "=r"(r[1]) : "r"(a));
}
__device__ __forceinline__ void ldsm2t(unsigned* r, unsigned a) {
    asm volatile("ldmatrix.sync.aligned.m8n8.x2.trans.shared.b16 {%0,%1}, [%2];"
        : "=r"(r[0]), "=r"(r[1]) : "r"(a));
}
__device__ __forceinline__ unsigned h2exp2(unsigned x) {
    unsigned r;
    asm("ex2.approx.f16x2 %0, %1;" : "=r"(r) : "r"(x));
    return r;
}

// ---------------------------------------------------------------------------
// Kernel 1: weight-norm scale, tf32 round, write FRAGMENT-SWIZZLED layout:
// g_w[ ((o/16)*64 + c/8)*128 + (g*4 + t4)*4 + i ]
//   where g=(o%16)&7, mh=(o%16)>>3, t4=c&3, kh=(c&7)>>2, i = mh + 2*kh.
// Each 128-float block is one warp's m16k8 A-fragment set (lane-major x4).
// ---------------------------------------------------------------------------
__global__ void prep_w(const float* __restrict__ pv,
                       const float* __restrict__ pg) {
    int o = blockIdx.x * 8 + (threadIdx.x >> 5);
    int lane = threadIdx.x & 31;
    const float* row = pv + (size_t)o * CC;
    float s = 0.f;
    #pragma unroll 4
    for (int i = lane; i < CC; i += 32) { float v = row[i]; s += v * v; }
    #pragma unroll
    for (int off = 16; off; off >>= 1) s += __shfl_xor_sync(0xffffffffu, s, off);
    float sc = pg[o] / sqrtf(s);

    const int m16 = o >> 4;
    const int g   = o & 7;
    const int mh  = (o >> 3) & 1;
    #pragma unroll 4
    for (int c = lane; c < CC; c += 32) {
        int k8 = c >> 3;
        int t4 = c & 3;
        int kh = (c >> 2) & 1;
        int idx = ((m16 * 64 + k8) * 32 + (g * 4 + t4)) * 4 + (mh + 2 * kh);
        g_w[idx] = tf32f(row[c] * sc);
    }
}

// ---------------------------------------------------------------------------
// Kernel 2: qkv = w @ x + b  (tf32 mma, 3-stage cp.async pipeline).
// CTA tile 128x128, k-tile 32, 8 warps 2m x 4n (64x32 warp tiles).
// A-fragments: one LDS.128 per fragment (pre-swizzled layout).
// Output written as fp16.
// ---------------------------------------------------------------------------
#define PK 32
#define XS_STR 136                       // Xs [32 k][128 n]
#define WS_FLOATS (128 * 32)             // 4096 (block-linear)
#define XS_FLOATS (PK * XS_STR)          // 4352
#define STAGE_FLOATS (WS_FLOATS + XS_FLOATS)
#define NSTG 3
#define PROJ_SMEM (NSTG * STAGE_FLOATS * 4)   // 101,376 B

__global__ __launch_bounds__(256, 2)
void proj_mma(const float* __restrict__ x,
              const float* __restrict__ pb) {
    extern __shared__ float psm[];

    const int b  = blockIdx.z;
    const int bm = blockIdx.y * 128;
    const int bn = blockIdx.x * 128;
    const float* xb = x + (size_t)b * CC * NN;
    __half* outp = g_qkvh + (size_t)b * O3 * NN;

    const int t    = threadIdx.x;
    const int w    = t >> 5;
    const int lane = t & 31;
    const int g    = lane >> 2;
    const int t4   = lane & 3;
    const int moff16 = (w & 1) * 4;      // warp m16-tile base
    const int noff   = (w >> 1) * 32;

    const unsigned base_u = smaddr(psm);

    float c[4][4][4];
    #pragma unroll
    for (int mf = 0; mf < 4; mf++)
        #pragma unroll
        for (int nf = 0; nf < 4; nf++)
            #pragma unroll
            for (int i = 0; i < 4; i++) c[mf][nf][i] = 0.f;

    // ---- async stage loader ----
    auto load_stage = [&](int stg, int kt) {
        unsigned sdst = base_u + stg * (STAGE_FLOATS * 4);
        int k0 = kt * PK;
        // W: 32 blocks of 128 floats (8 m16-tiles x 4 k8-chunks), block-linear
        #pragma unroll
        for (int i = 0; i < 4; i++) {
            int j = t + i * 256;             // 1024 chunks of 16B
            int blk = j >> 5, ln = j & 31;   // blk: m16l*4 + k8l
            int m16l = blk >> 2, k8l = blk & 3;
            cpa16(sdst + (unsigned)(blk * 128 + ln * 4) * 4,
                  g_w + ((size_t)((bm >> 4) + m16l) * 64 + (k0 >> 3) + k8l) * 128 + ln * 4);
        }
        // X: 32 rows x 128 cols fp32
        unsigned xdst = sdst + WS_FLOATS * 4;
        #pragma unroll
        for (int i = 0; i < 4; i++) {
            int idx = t + i * 256;
            int r = idx >> 5, n4 = idx & 31;
            cpa16(xdst + (unsigned)(r * XS_STR + n4 * 4) * 4,
                  xb + (size_t)(k0 + r) * NN + bn + n4 * 4);
        }
    };

    load_stage(0, 0); cp_commit();
    load_stage(1, 1); cp_commit();

    for (int kt = 0; kt < 16; kt++) {
        cp_wait<1>();
        __syncthreads();
        if (kt + 2 < 16) load_stage((kt + 2) % NSTG, kt + 2);
        cp_commit();

        const float* Wc = psm + (kt % NSTG) * STAGE_FLOATS;
        const float* Xc = Wc + WS_FLOATS;

        #pragma unroll
        for (int ks = 0; ks < 4; ks++) {
            const int koff = ks * 8;
            unsigned a[4][4], bf[4][2];
            #pragma unroll
            for (int mf = 0; mf < 4; mf++) {
                float4 av = *(const float4*)(Wc + ((moff16 + mf) * 4 + ks) * 128 + lane * 4);
                a[mf][0] = __float_as_uint(av.x);
                a[mf][1] = __float_as_uint(av.y);
                a[mf][2] = __float_as_uint(av.z);
                a[mf][3] = __float_as_uint(av.w);
            }
            #pragma unroll
            for (int nf = 0; nf < 4; nf++) {
                int col = noff + nf * 8 + g;
                bf[nf][0] = __float_as_uint(Xc[(koff + t4)     * XS_STR + col]);
                bf[nf][1] = __float_as_uint(Xc[(koff + t4 + 4) * XS_STR + col]);
            }
            #pragma unroll
            for (int mf = 0; mf < 4; mf++)
                #pragma unroll
                for (int nf = 0; nf < 4; nf++)
                    mma8(c[mf][nf], a[mf], bf[nf]);
        }
    }

    // Epilogue: bias + store fp16
    #pragma unroll
    for (int mf = 0; mf < 4; mf++) {
        int o = bm + (moff16 + mf) * 16 + g;
        float bias0 = pb[o], bias1 = pb[o + 8];
        #pragma unroll
        for (int nf = 0; nf < 4; nf++) {
            int n = bn + noff + nf * 8 + 2 * t4;
            *(__half2*)(outp + (size_t)o * NN + n) =
                __floats2half2_rn(c[mf][nf][0] + bias0, c[mf][nf][1] + bias0);
            *(__half2*)(outp + (size_t)(o + 8) * NN + n) =
                __floats2half2_rn(c[mf][nf][2] + bias1, c[mf][nf][3] + bias1);
        }
    }
}

// ---------------------------------------------------------------------------
// Kernel 3: flash attention, fp16 m16n8k16 mma + ldmatrix + cp.async pipeline.
// K double-buffered (prefetch overlaps softmax+GEMM2); V issued at iter top,
// awaited before GEMM2 (overlaps GEMM1+softmax). exp via ex2.approx.f16x2;
// 1/8 scale folded into the exp2 constant. P stored as fp16 directly.
// ---------------------------------------------------------------------------
#define STR 136          // halves per row (272B = 17 x 16B, ldmatrix CF)
#define KTILE_B 17408    // 64*136*2
#define QS_OFF   0
#define KS_OFF   17408
#define VS_OFF   52224   // after 2 K buffers
#define PB_OFF   69632
#define PMAX_OFF 104448
#define PSUM_OFF 106496
#define ROWM_OFF 108544
#define ROWL_OFF 109056
#define ROWF_OFF 109568
#define ATTN_SMEM 110080

__global__ __launch_bounds__(256, 2)
void attn_mma(const float* __restrict__ x, float* __restrict__ out) {
    extern __shared__ char smc[];
    __half* Pb = (__half*)(smc + PB_OFF);
    float* pmax = (float*)(smc + PMAX_OFF);   // [4][128]
    float* psum = (float*)(smc + PSUM_OFF);   // [4][128]
    float* rowm = (float*)(smc + ROWM_OFF);
    float* rowl = (float*)(smc + ROWL_OFF);
    float* rowf = (float*)(smc + ROWF_OFF);

    const int t    = threadIdx.x;
    const int w    = t >> 5;
    const int lane = t & 31;
    const int g    = lane >> 2;
    const int t4   = lane & 3;
    const int bh   = blockIdx.y;
    const int b    = bh >> 3, h = bh & 7;
    const int q0   = blockIdx.x * 128;

    const int half  = w & 1;
    const int cg    = w >> 1;
    const int m1off = half * 64;
    const int n1off = cg * 32;
    const int m2off = half * 64;
    const int n2off = cg * 16;

    const __half* Qg = g_qkvh + ((size_t)b * O3 + h * DIM) * NN;
    const __half* Kg = Qg + (size_t)CC * NN;
    const __half* Vg = Qg + (size_t)2 * CC * NN;

    const unsigned qs_u = smaddr(smc + QS_OFF);
    const unsigned ks_u = smaddr(smc + KS_OFF);
    const unsigned vs_u = smaddr(smc + VS_OFF);
    const unsigned pb_u = smaddr(Pb);

    // ldmatrix per-lane address components
    const int rAt = ((lane & 16) >> 1) + (lane & 7);
    const int cAt = lane & 8;
    const int rBt = (lane & 8) + (lane & 7);
    const int rA2 = (lane & 8) + (lane & 7);
    const int cA2 = (lane & 16) >> 1;
    const int rB2 = lane & 7;
    const int cB2 = lane & 8;

    const int ld_d  = t >> 4;          // tile-load row helper (64 rows, 4 iters)
    const int ld_c8 = t & 15;

    // Prologue: async-load Q tile + K(0); one group
    #pragma unroll
    for (int i = 0; i < 4; i++) {
        int d = ld_d + i * 16;
        cpa16(qs_u + (unsigned)(d * STR + ld_c8 * 8) * 2,
              Qg + (size_t)d * NN + q0 + ld_c8 * 8);
        cpa16(ks_u + (unsigned)(d * STR + ld_c8 * 8) * 2,
              Kg + (size_t)d * NN + 0 + ld_c8 * 8);
    }
    cp_commit();

    if (t < 128) { rowm[t] = -3.0e38f; rowl[t] = 0.f; }

    float Oa[4][2][4];
    #pragma unroll
    for (int mf = 0; mf < 4; mf++)
        #pragma unroll
        for (int nf = 0; nf < 2; nf++)
            #pragma unroll
            for (int i = 0; i < 4; i++) Oa[mf][nf][i] = 0.f;

    const float CE = 0.18033688f;   // 0.125 * log2(e)

    for (int it = 0; it < 8; it++) {
        const int k0 = it * 128;
        cp_wait<0>();                 // K(it) (and any prior V) complete
        __syncthreads();              // Vs free (GEMM2 it-1 done by all)

        // issue V(it) — awaited before GEMM2
        #pragma unroll
        for (int i = 0; i < 4; i++) {
            int d = ld_d + i * 16;
            cpa16(vs_u + (unsigned)(d * STR + ld_c8 * 8) * 2,
                  Vg + (size_t)d * NN + k0 + ld_c8 * 8);
        }
        cp_commit();

        const unsigned ks_cur = ks_u + (unsigned)(it & 1) * KTILE_B;

        // ---- GEMM1: S[q][k] = Q^T K (fp16, raw scale) ----
        float c1[4][4][4];
        #pragma unroll
        for (int mf = 0; mf < 4; mf++)
            #pragma unroll
            for (int nf = 0; nf < 4; nf++)
                #pragma unroll
                for (int i = 0; i < 4; i++) c1[mf][nf][i] = 0.f;

        #pragma unroll
        for (int ks = 0; ks < 4; ks++) {
            const int koff = ks * 16;
            unsigned a[4][4], bq[4][2];
            #pragma unroll
            for (int mf = 0; mf < 4; mf++)
                ldsm4t(a[mf], qs_u +
                    (unsigned)(((koff + rAt) * STR + m1off + mf * 16 + cAt) * 2));
            #pragma unroll
            for (int nf = 0; nf < 4; nf++)
                ldsm2t(bq[nf], ks_cur +
                    (unsigned)(((koff + rBt) * STR + n1off + nf * 8) * 2));
            #pragma unroll
            for (int mf = 0; mf < 4; mf++)
                #pragma unroll
                for (int nf = 0; nf < 4; nf++)
                    mma16h(c1[mf][nf], a[mf], bq[nf]);
        }

        // prefetch K(it+1) into other buffer (overlaps softmax + GEMM2)
        if (it < 7) {
            const unsigned ks_nxt = ks_u + (unsigned)((it + 1) & 1) * KTILE_B;
            #pragma unroll
            for (int i = 0; i < 4; i++) {
                int d = ld_d + i * 16;
                cpa16(ks_nxt + (unsigned)(d * STR + ld_c8 * 8) * 2,
                      Kg + (size_t)d * NN + (k0 + 128) + ld_c8 * 8);
            }
        }
        cp_commit();                  // always commit (empty on last iter)

        // ---- softmax phase 1: per-warp row maxima (unscaled S) ----
        #pragma unroll
        for (int mf = 0; mf < 4; mf++) {
            float m0 = -3.0e38f, m1 = -3.0e38f;
            #pragma unroll
            for (int nf = 0; nf < 4; nf++) {
                m0 = fmaxf(m0, fmaxf(c1[mf][nf][0], c1[mf][nf][1]));
                m1 = fmaxf(m1, fmaxf(c1[mf][nf][2], c1[mf][nf][3]));
            }
            m0 = fmaxf(m0, __shfl_xor_sync(0xffffffffu, m0, 1));
            m0 = fmaxf(m0, __shfl_xor_sync(0xffffffffu, m0, 2));
            m1 = fmaxf(m1, __shfl_xor_sync(0xffffffffu, m1, 1));
            m1 = fmaxf(m1, __shfl_xor_sync(0xffffffffu, m1, 2));
            if (t4 == 0) {
                int r = m1off + mf * 16 + g;
                pmax[cg * 128 + r]     = m0;
                pmax[cg * 128 + r + 8] = m1;
            }
        }
        __syncthreads();

        // ---- phase 2: p = exp2((s-nm)*CE) via f16x2 MUFU; P -> fp16 SMEM ----
        #pragma unroll
        for (int mf = 0; mf < 4; mf++) {
            int r0 = m1off + mf * 16 + g;
            int r1 = r0 + 8;
            float nm0 = fmaxf(fmaxf(fmaxf(pmax[r0], pmax[128 + r0]),
                                    fmaxf(pmax[256 + r0], pmax[384 + r0])), rowm[r0]);
            float nm1 = fmaxf(fmaxf(fmaxf(pmax[r1], pmax[128 + r1]),
                                    fmaxf(pmax[256 + r1], pmax[384 + r1])), rowm[r1]);
            float s0 = 0.f, s1 = 0.f;
            #pragma unroll
            for (int nf = 0; nf < 4; nf++) {
                __half2 ha = __floats2half2_rn((c1[mf][nf][0] - nm0) * CE,
                                               (c1[mf][nf][1] - nm0) * CE);
                __half2 hb = __floats2half2_rn((c1[mf][nf][2] - nm1) * CE,
                                               (c1[mf][nf][3] - nm1) * CE);
                unsigned pa = h2exp2(*(unsigned*)&ha);
                unsigned pc = h2exp2(*(unsigned*)&hb);
                float2 fa = __half22float2(*(__half2*)&pa);
                float2 fc = __half22float2(*(__half2*)&pc);
                s0 += fa.x + fa.y;
                s1 += fc.x + fc.y;
                int col = n1off + nf * 8 + 2 * t4;
                *(unsigned*)(Pb + r0 * STR + col) = pa;
                *(unsigned*)(Pb + r1 * STR + col) = pc;
            }
            s0 += __shfl_xor_sync(0xffffffffu, s0, 1);
            s0 += __shfl_xor_sync(0xffffffffu, s0, 2);
            s1 += __shfl_xor_sync(0xffffffffu, s1, 1);
            s1 += __shfl_xor_sync(0xffffffffu, s1, 2);
            if (t4 == 0) {
                psum[cg * 128 + r0] = s0;
                psum[cg * 128 + r1] = s1;
            }
        }
        __syncthreads();

        // ---- phase 3: row-state update ----
        if (t < 128) {
            float old = rowm[t];
            float nm = fmaxf(fmaxf(fmaxf(pmax[t], pmax[128 + t]),
                                   fmaxf(pmax[256 + t], pmax[384 + t])), old);
            float f = exp2f((old - nm) * CE);
            rowl[t] = rowl[t] * f +
                      (psum[t] + psum[128 + t] + psum[256 + t] + psum[384 + t]);
            rowm[t] = nm;
            rowf[t] = f;
        }
        cp_wait<1>();                 // V(it) done (K(it+1) may still fly)
        __syncthreads();

        // ---- rescale O, then GEMM2: O[q][d] += P V^T ----
        #pragma unroll
        for (int mf = 0; mf < 4; mf++) {
            float f0 = rowf[m2off + mf * 16 + g];
            float f1 = rowf[m2off + mf * 16 + g + 8];
            #pragma unroll
            for (int nf = 0; nf < 2; nf++) {
                Oa[mf][nf][0] *= f0; Oa[mf][nf][1] *= f0;
                Oa[mf][nf][2] *= f1; Oa[mf][nf][3] *= f1;
            }
        }
        #pragma unroll
        for (int ks = 0; ks < 8; ks++) {
            const int koff = ks * 16;
            unsigned a[4][4], bv[2][2];
            #pragma unroll
            for (int mf = 0; mf < 4; mf++)
                ldsm4(a[mf], pb_u +
                    (unsigned)(((m2off + mf * 16 + rA2) * STR + koff + cA2) * 2));
            #pragma unroll
            for (int nf = 0; nf < 2; nf++)
                ldsm2(bv[nf], vs_u +
                    (unsigned)(((n2off + nf * 8 + rB2) * STR + koff + cB2) * 2));
            #pragma unroll
            for (int mf = 0; mf < 4; mf++)
                #pragma unroll
                for (int nf = 0; nf < 2; nf++)
                    mma16h(Oa[mf][nf], a[mf], bv[nf]);
        }
    }

    // Epilogue: out[b, h*64+d, q0+q] = x + O/l
    const size_t base = ((size_t)b * CC + h * DIM) * NN + q0;
    #pragma unroll
    for (int mf = 0; mf < 4; mf++) {
        int q = m2off + mf * 16 + g;
        float inv0 = 1.f / rowl[q];
        float inv1 = 1.f / rowl[q + 8];
        #pragma unroll
        for (int nf = 0; nf < 2; nf++) {
            int d = n2off + nf * 8 + 2 * t4;
            size_t a0 = base + (size_t)d * NN + q;
            out[a0]      = x[a0]      + Oa[mf][nf][0] * inv0;
            out[a0 + NN] = x[a0 + NN] + Oa[mf][nf][1] * inv0;
            size_t a2 = a0 + 8;
            out[a2]      = x[a2]      + Oa[mf][nf][2] * inv1;
            out[a2 + NN] = x[a2 + NN] + Oa[mf][nf][3] * inv1;
        }
    }
}

// ---------------------------------------------------------------------------
// Launch
// ---------------------------------------------------------------------------
extern "C" void kernel_launch(void* const* d_in, const int* in_sizes, int n_in,
                              void* d_out, int out_size) {
    const float* x  = (const float*)d_in[0];
    const float* pv = (const float*)d_in[1];
    const float* pg = (const float*)d_in[2];
    const float* pb = (const float*)d_in[3];
    float* out = (float*)d_out;

    prep_w<<<O3 / 8, 256>>>(pv, pg);

    cudaFuncSetAttribute(proj_mma,
                         cudaFuncAttributeMaxDynamicSharedMemorySize, PROJ_SMEM);
    dim3 pgrid(NN / 128, O3 / 128, BB);
    proj_mma<<<pgrid, 256, PROJ_SMEM>>>(x, pb);

    cudaFuncSetAttribute(attn_mma,
                         cudaFuncAttributeMaxDynamicSharedMemorySize, ATTN_SMEM);
    dim3 agrid(NN / 128, BB * HEADS);
    attn_mma<<<agrid, 256, ATTN_SMEM>>>(x, out);
}

// round 10
// speedup vs baseline: 5.2968x; 1.0390x over previous
#include <cuda_runtime.h>
#include <cuda_fp16.h>
#include <math.h>

// Problem constants
#define CC    512      // channels
#define O3    1536     // 3*C
#define NN    1024     // H*W
#define BB    8        // batch
#define DIM   64       // head dim
#define HEADS 8

// ---------------------------------------------------------------------------
// Scratch
// ---------------------------------------------------------------------------
__device__ __half g_wh[(size_t)O3 * CC];              // fp16 weight-normed W
__device__ __half g_xh[(size_t)BB * CC * NN];         // fp16 x
__device__ __half g_qkvh[(size_t)BB * O3 * NN];       // 25 MB fp16 qkv

// ---------------------------------------------------------------------------
// helpers
// ---------------------------------------------------------------------------
__device__ __forceinline__ unsigned smaddr(const void* p) {
    return (unsigned)__cvta_generic_to_shared(p);
}
__device__ __forceinline__ void cpa16(unsigned dst, const void* src) {
    asm volatile("cp.async.cg.shared.global [%0], [%1], 16;" :: "r"(dst), "l"(src));
}
__device__ __forceinline__ void cp_commit() {
    asm volatile("cp.async.commit_group;");
}
template<int N> __device__ __forceinline__ void cp_wait() {
    asm volatile("cp.async.wait_group %0;" :: "n"(N));
}
__device__ __forceinline__ void mma16h(float* c, const unsigned* a, const unsigned* b) {
    asm volatile(
        "mma.sync.aligned.m16n8k16.row.col.f32.f16.f16.f32 "
        "{%0,%1,%2,%3}, {%4,%5,%6,%7}, {%8,%9}, {%0,%1,%2,%3};\n"
        : "+f"(c[0]), "+f"(c[1]), "+f"(c[2]), "+f"(c[3])
        : "r"(a[0]), "r"(a[1]), "r"(a[2]), "r"(a[3]), "r"(b[0]), "r"(b[1]));
}
__device__ __forceinline__ void ldsm4(unsigned* r, unsigned a) {
    asm volatile("ldmatrix.sync.aligned.m8n8.x4.shared.b16 {%0,%1,%2,%3}, [%4];"
        : "=r"(r[0]), "=r"(r[1]), "=r"(r[2]), "=r"(r[3]) : "r"(a));
}
__device__ __forceinline__ void ldsm4t(unsigned* r, unsigned a) {
    asm volatile("ldmatrix.sync.aligned.m8n8.x4.trans.shared.b16 {%0,%1,%2,%3}, [%4];"
        : "=r"(r[0]), "=r"(r[1]), "=r"(r[2]), "=r"(r[3]) : "r"(a));
}
__device__ __forceinline__ void ldsm2(unsigned* r, unsigned a) {
    asm volatile("ldmatrix.sync.aligned.m8n8.x2.shared.b16 {%0,%1}, [%2];"
        : "=r"(r[0]), "=r"(r[1]) : "r"(a));
}
__device__ __forceinline__ void ldsm2t(unsigned* r, unsigned a) {
    asm volatile("ldmatrix.sync.aligned.m8n8.x2.trans.shared.b16 {%0,%1}, [%2];"
        : "=r"(r[0]), "=r"(r[1]) : "r"(a));
}
__device__ __forceinline__ unsigned h2exp2(unsigned x) {
    unsigned r;
    asm("ex2.approx.f16x2 %0, %1;" : "=r"(r) : "r"(x));
    return r;
}

// ---------------------------------------------------------------------------
// Kernel 0: x -> fp16
// ---------------------------------------------------------------------------
__global__ void convert_x(const float* __restrict__ x) {
    size_t i = ((size_t)blockIdx.x * 256 + threadIdx.x) * 4;
    float4 v = *(const float4*)(x + i);
    *(__half2*)(g_xh + i)     = __floats2half2_rn(v.x, v.y);
    *(__half2*)(g_xh + i + 2) = __floats2half2_rn(v.z, v.w);
}

// ---------------------------------------------------------------------------
// Kernel 1: w[o][c] = fp16( proj_g[o]/||proj_v[o,:]|| * proj_v[o][c] )
// ---------------------------------------------------------------------------
__global__ void prep_w(const float* __restrict__ pv,
                       const float* __restrict__ pg) {
    int o = blockIdx.x * 8 + (threadIdx.x >> 5);
    int lane = threadIdx.x & 31;
    const float* row = pv + (size_t)o * CC;
    float s = 0.f;
    #pragma unroll 4
    for (int i = lane; i < CC; i += 32) { float v = row[i]; s += v * v; }
    #pragma unroll
    for (int off = 16; off; off >>= 1) s += __shfl_xor_sync(0xffffffffu, s, off);
    float sc = pg[o] / sqrtf(s);
    #pragma unroll 4
    for (int c = lane * 2; c < CC; c += 64)
        *(__half2*)(g_wh + (size_t)o * CC + c) =
            __floats2half2_rn(row[c] * sc, row[c + 1] * sc);
}

// ---------------------------------------------------------------------------
// Kernel 2: qkv = w @ x + b  (fp16 m16n8k16 mma, ldmatrix, 4-stage cp.async).
// CTA tile 128x128, k-tile 32, 8 warps 2m x 4n (64x32 warp tiles).
// ---------------------------------------------------------------------------
#define PK 32
#define WTS 40                           // W tile stride (halves): 80B=5x16B CF
#define XTS 136                          // X tile stride (halves): 17x16B CF
#define W_HALFS (128 * WTS)              // 5120
#define X_HALFS (PK * XTS)               // 4352
#define STG_B ((W_HALFS + X_HALFS) * 2)  // 18944
#define NSTG 4
#define PROJ_SMEM (NSTG * STG_B)         // 75,776 B

__global__ __launch_bounds__(256, 2)
void proj_mma(const float* __restrict__ pb) {
    extern __shared__ char psmc[];

    const int b  = blockIdx.z;
    const int bm = blockIdx.y * 128;
    const int bn = blockIdx.x * 128;
    const __half* xb = g_xh + (size_t)b * CC * NN;
    __half* outp = g_qkvh + (size_t)b * O3 * NN;

    const int t    = threadIdx.x;
    const int w    = t >> 5;
    const int lane = t & 31;
    const int g    = lane >> 2;
    const int t4   = lane & 3;
    const int moff = (w & 1) * 64;
    const int noff = (w >> 1) * 32;

    const unsigned base_u = smaddr(psmc);
    const int rA = (lane & 8) + (lane & 7);    // ldsm4 A rows / ldsm2t B rows
    const int cA = (lane & 16) >> 1;           // ldsm4 A col offset (halves)

    float c[4][4][4];
    #pragma unroll
    for (int mf = 0; mf < 4; mf++)
        #pragma unroll
        for (int nf = 0; nf < 4; nf++)
            #pragma unroll
            for (int i = 0; i < 4; i++) c[mf][nf][i] = 0.f;

    // ---- async stage loader: W 512 chunks + X 512 chunks of 16B ----
    auto load_stage = [&](int stg, int kt) {
        unsigned sd = base_u + stg * STG_B;
        int k0 = kt * PK;
        #pragma unroll
        for (int i = 0; i < 2; i++) {
            int idx = t + i * 256;               // 0..511
            int r = idx >> 2, c8 = idx & 3;      // W: [128 m][4 x 8 halves]
            cpa16(sd + (unsigned)(r * WTS + c8 * 8) * 2,
                  g_wh + (size_t)(bm + r) * CC + k0 + c8 * 8);
        }
        unsigned xd = sd + W_HALFS * 2;
        #pragma unroll
        for (int i = 0; i < 2; i++) {
            int idx = t + i * 256;
            int r = idx >> 4, c8 = idx & 15;     // X: [32 k][16 x 8 halves]
            cpa16(xd + (unsigned)(r * XTS + c8 * 8) * 2,
                  xb + (size_t)(k0 + r) * NN + bn + c8 * 8);
        }
    };

    load_stage(0, 0); cp_commit();
    load_stage(1, 1); cp_commit();
    load_stage(2, 2); cp_commit();

    for (int kt = 0; kt < 16; kt++) {
        cp_wait<2>();
        __syncthreads();
        if (kt + 3 < 16) load_stage((kt + 3) % NSTG, kt + 3);
        cp_commit();

        const unsigned wcur = base_u + (kt % NSTG) * STG_B;
        const unsigned xcur = wcur + W_HALFS * 2;

        #pragma unroll
        for (int ks = 0; ks < 2; ks++) {
            const int koff = ks * 16;
            unsigned a[4][4], bq[4][2];
            #pragma unroll
            for (int mf = 0; mf < 4; mf++)
                ldsm4(a[mf], wcur +
                    (unsigned)(((moff + mf * 16 + rA) * WTS + koff + cA) * 2));
            #pragma unroll
            for (int nf = 0; nf < 4; nf++)
                ldsm2t(bq[nf], xcur +
                    (unsigned)(((koff + rA) * XTS + noff + nf * 8) * 2));
            #pragma unroll
            for (int mf = 0; mf < 4; mf++)
                #pragma unroll
                for (int nf = 0; nf < 4; nf++)
                    mma16h(c[mf][nf], a[mf], bq[nf]);
        }
    }

    // Epilogue: bias + store fp16
    #pragma unroll
    for (int mf = 0; mf < 4; mf++) {
        int o = bm + moff + mf * 16 + g;
        float bias0 = pb[o], bias1 = pb[o + 8];
        #pragma unroll
        for (int nf = 0; nf < 4; nf++) {
            int n = bn + noff + nf * 8 + 2 * t4;
            *(__half2*)(outp + (size_t)o * NN + n) =
                __floats2half2_rn(c[mf][nf][0] + bias0, c[mf][nf][1] + bias0);
            *(__half2*)(outp + (size_t)(o + 8) * NN + n) =
                __floats2half2_rn(c[mf][nf][2] + bias1, c[mf][nf][3] + bias1);
        }
    }
}

// ---------------------------------------------------------------------------
// Kernel 3: flash attention, fp16 mma + ldmatrix + cp.async pipeline.
// Row state (m,l) register-resident per warp (dup across t4); 3 barriers/iter.
// ---------------------------------------------------------------------------
#define STR 136          // halves per row
#define KTILE_B 17408    // 64*136*2
#define QS_OFF   0
#define KS_OFF   17408
#define VS_OFF   52224   // after 2 K buffers
#define PB_OFF   69632
#define PMAX_OFF 104448  // float[4][128]
#define PSUM_OFF 106496  // float[4][128]
#define ATTN_SMEM 108544

__global__ __launch_bounds__(256, 2)
void attn_mma(const float* __restrict__ x, float* __restrict__ out) {
    extern __shared__ char smc[];
    __half* Pb = (__half*)(smc + PB_OFF);
    float* pmax = (float*)(smc + PMAX_OFF);
    float* psum = (float*)(smc + PSUM_OFF);

    const int t    = threadIdx.x;
    const int w    = t >> 5;
    const int lane = t & 31;
    const int g    = lane >> 2;
    const int t4   = lane & 3;
    const int bh   = blockIdx.y;
    const int b    = bh >> 3, h = bh & 7;
    const int q0   = blockIdx.x * 128;

    const int half  = w & 1;
    const int cg    = w >> 1;
    const int m1off = half * 64;
    const int n1off = cg * 32;
    const int n2off = cg * 16;

    const __half* Qg = g_qkvh + ((size_t)b * O3 + h * DIM) * NN;
    const __half* Kg = Qg + (size_t)CC * NN;
    const __half* Vg = Qg + (size_t)2 * CC * NN;

    const unsigned qs_u = smaddr(smc + QS_OFF);
    const unsigned ks_u = smaddr(smc + KS_OFF);
    const unsigned vs_u = smaddr(smc + VS_OFF);
    const unsigned pb_u = smaddr(Pb);

    // ldmatrix per-lane address components
    const int rAt = ((lane & 16) >> 1) + (lane & 7);
    const int cAt = lane & 8;
    const int rBt = (lane & 8) + (lane & 7);
    const int rA2 = (lane & 8) + (lane & 7);
    const int cA2 = (lane & 16) >> 1;
    const int rB2 = lane & 7;
    const int cB2 = lane & 8;

    const int ld_d  = t >> 4;
    const int ld_c8 = t & 15;

    // Prologue: async Q tile + K(0)
    #pragma unroll
    for (int i = 0; i < 4; i++) {
        int d = ld_d + i * 16;
        cpa16(qs_u + (unsigned)(d * STR + ld_c8 * 8) * 2,
              Qg + (size_t)d * NN + q0 + ld_c8 * 8);
        cpa16(ks_u + (unsigned)(d * STR + ld_c8 * 8) * 2,
              Kg + (size_t)d * NN + 0 + ld_c8 * 8);
    }
    cp_commit();

    float Oa[4][2][4];
    #pragma unroll
    for (int mf = 0; mf < 4; mf++)
        #pragma unroll
        for (int nf = 0; nf < 2; nf++)
            #pragma unroll
            for (int i = 0; i < 4; i++) Oa[mf][nf][i] = 0.f;

    float lm[4][2], ll[4][2];      // per-warp row state (dup across t4)
    #pragma unroll
    for (int mf = 0; mf < 4; mf++) {
        lm[mf][0] = lm[mf][1] = -3.0e38f;
        ll[mf][0] = ll[mf][1] = 0.f;
    }

    const float CE = 0.18033688f;   // 0.125 * log2(e)

    for (int it = 0; it < 8; it++) {
        const int k0 = it * 128;
        cp_wait<0>();
        __syncthreads();              // K(it) visible; Vs free

        // issue V(it)
        #pragma unroll
        for (int i = 0; i < 4; i++) {
            int d = ld_d + i * 16;
            cpa16(vs_u + (unsigned)(d * STR + ld_c8 * 8) * 2,
                  Vg + (size_t)d * NN + k0 + ld_c8 * 8);
        }
        cp_commit();

        const unsigned ks_cur = ks_u + (unsigned)(it & 1) * KTILE_B;

        // ---- GEMM1: S[q][k] = Q^T K ----
        float c1[4][4][4];
        #pragma unroll
        for (int mf = 0; mf < 4; mf++)
            #pragma unroll
            for (int nf = 0; nf < 4; nf++)
                #pragma unroll
                for (int i = 0; i < 4; i++) c1[mf][nf][i] = 0.f;

        #pragma unroll
        for (int ks = 0; ks < 4; ks++) {
            const int koff = ks * 16;
            unsigned a[4][4], bq[4][2];
            #pragma unroll
            for (int mf = 0; mf < 4; mf++)
                ldsm4t(a[mf], qs_u +
                    (unsigned)(((koff + rAt) * STR + m1off + mf * 16 + cAt) * 2));
            #pragma unroll
            for (int nf = 0; nf < 4; nf++)
                ldsm2t(bq[nf], ks_cur +
                    (unsigned)(((koff + rBt) * STR + n1off + nf * 8) * 2));
            #pragma unroll
            for (int mf = 0; mf < 4; mf++)
                #pragma unroll
                for (int nf = 0; nf < 4; nf++)
                    mma16h(c1[mf][nf], a[mf], bq[nf]);
        }

        // prefetch K(it+1)
        if (it < 7) {
            const unsigned ks_nxt = ks_u + (unsigned)((it + 1) & 1) * KTILE_B;
            #pragma unroll
            for (int i = 0; i < 4; i++) {
                int d = ld_d + i * 16;
                cpa16(ks_nxt + (unsigned)(d * STR + ld_c8 * 8) * 2,
                      Kg + (size_t)d * NN + (k0 + 128) + ld_c8 * 8);
            }
        }
        cp_commit();

        // ---- phase 1: per-warp row maxima -> pmax ----
        #pragma unroll
        for (int mf = 0; mf < 4; mf++) {
            float m0 = -3.0e38f, m1 = -3.0e38f;
            #pragma unroll
            for (int nf = 0; nf < 4; nf++) {
                m0 = fmaxf(m0, fmaxf(c1[mf][nf][0], c1[mf][nf][1]));
                m1 = fmaxf(m1, fmaxf(c1[mf][nf][2], c1[mf][nf][3]));
            }
            m0 = fmaxf(m0, __shfl_xor_sync(0xffffffffu, m0, 1));
            m0 = fmaxf(m0, __shfl_xor_sync(0xffffffffu, m0, 2));
            m1 = fmaxf(m1, __shfl_xor_sync(0xffffffffu, m1, 1));
            m1 = fmaxf(m1, __shfl_xor_sync(0xffffffffu, m1, 2));
            if (t4 == 0) {
                int r = m1off + mf * 16 + g;
                pmax[cg * 128 + r]     = m0;
                pmax[cg * 128 + r + 8] = m1;
            }
        }
        __syncthreads();

        // ---- phase 2: nm from pmax+lm; exp (f16x2); write Pb + psum ----
        #pragma unroll
        for (int mf = 0; mf < 4; mf++) {
            int r0 = m1off + mf * 16 + g;
            int r1 = r0 + 8;
            float nm0 = fmaxf(fmaxf(fmaxf(pmax[r0], pmax[128 + r0]),
                                    fmaxf(pmax[256 + r0], pmax[384 + r0])), lm[mf][0]);
            float nm1 = fmaxf(fmaxf(fmaxf(pmax[r1], pmax[128 + r1]),
                                    fmaxf(pmax[256 + r1], pmax[384 + r1])), lm[mf][1]);
            float s0 = 0.f, s1 = 0.f;
            #pragma unroll
            for (int nf = 0; nf < 4; nf++) {
                __half2 ha = __floats2half2_rn((c1[mf][nf][0] - nm0) * CE,
                                               (c1[mf][nf][1] - nm0) * CE);
                __half2 hb = __floats2half2_rn((c1[mf][nf][2] - nm1) * CE,
                                               (c1[mf][nf][3] - nm1) * CE);
                unsigned pa = h2exp2(*(unsigned*)&ha);
                unsigned pc = h2exp2(*(unsigned*)&hb);
                float2 fa = __half22float2(*(__half2*)&pa);
                float2 fc = __half22float2(*(__half2*)&pc);
                s0 += fa.x + fa.y;
                s1 += fc.x + fc.y;
                int col = n1off + nf * 8 + 2 * t4;
                *(unsigned*)(Pb + r0 * STR + col) = pa;
                *(unsigned*)(Pb + r1 * STR + col) = pc;
            }
            s0 += __shfl_xor_sync(0xffffffffu, s0, 1);
            s0 += __shfl_xor_sync(0xffffffffu, s0, 2);
            s1 += __shfl_xor_sync(0xffffffffu, s1, 1);
            s1 += __shfl_xor_sync(0xffffffffu, s1, 2);
            if (t4 == 0) {
                psum[cg * 128 + r0] = s0;
                psum[cg * 128 + r1] = s1;
            }
        }
        cp_wait<1>();                 // V(it) done (K(it+1) may still fly)
        __syncthreads();              // Pb + psum + Vs visible

        // ---- local row-state update + O rescale ----
        #pragma unroll
        for (int mf = 0; mf < 4; mf++) {
            int r0 = m1off + mf * 16 + g;
            int r1 = r0 + 8;
            float nm0 = fmaxf(fmaxf(fmaxf(pmax[r0], pmax[128 + r0]),
                                    fmaxf(pmax[256 + r0], pmax[384 + r0])), lm[mf][0]);
            float nm1 = fmaxf(fmaxf(fmaxf(pmax[r1], pmax[128 + r1]),
                                    fmaxf(pmax[256 + r1], pmax[384 + r1])), lm[mf][1]);
            float sum0 = psum[r0] + psum[128 + r0] + psum[256 + r0] + psum[384 + r0];
            float sum1 = psum[r1] + psum[128 + r1] + psum[256 + r1] + psum[384 + r1];
            float f0 = exp2f((lm[mf][0] - nm0) * CE);
            float f1 = exp2f((lm[mf][1] - nm1) * CE);
            ll[mf][0] = ll[mf][0] * f0 + sum0;
            ll[mf][1] = ll[mf][1] * f1 + sum1;
            lm[mf][0] = nm0;
            lm[mf][1] = nm1;
            #pragma unroll
            for (int nf = 0; nf < 2; nf++) {
                Oa[mf][nf][0] *= f0; Oa[mf][nf][1] *= f0;
                Oa[mf][nf][2] *= f1; Oa[mf][nf][3] *= f1;
            }
        }

        // ---- GEMM2: O[q][d] += P V^T ----
        #pragma unroll
        for (int ks = 0; ks < 8; ks++) {
            const int koff = ks * 16;
            unsigned a[4][4], bv[2][2];
            #pragma unroll
            for (int mf = 0; mf < 4; mf++)
                ldsm4(a[mf], pb_u +
                    (unsigned)(((m1off + mf * 16 + rA2) * STR + koff + cA2) * 2));
            #pragma unroll
            for (int nf = 0; nf < 2; nf++)
                ldsm2(bv[nf], vs_u +
                    (unsigned)(((n2off + nf * 8 + rB2) * STR + koff + cB2) * 2));
            #pragma unroll
            for (int mf = 0; mf < 4; mf++)
                #pragma unroll
                for (int nf = 0; nf < 2; nf++)
                    mma16h(Oa[mf][nf], a[mf], bv[nf]);
        }
    }

    // Epilogue: out[b, h*64+d, q0+q] = x + O/l
    const size_t base = ((size_t)b * CC + h * DIM) * NN + q0;
    #pragma unroll
    for (int mf = 0; mf < 4; mf++) {
        int q = m1off + mf * 16 + g;
        float inv0 = 1.f / ll[mf][0];
        float inv1 = 1.f / ll[mf][1];
        #pragma unroll
        for (int nf = 0; nf < 2; nf++) {
            int d = n2off + nf * 8 + 2 * t4;
            size_t a0 = base + (size_t)d * NN + q;
            out[a0]      = x[a0]      + Oa[mf][nf][0] * inv0;
            out[a0 + NN] = x[a0 + NN] + Oa[mf][nf][1] * inv0;
            size_t a2 = a0 + 8;
            out[a2]      = x[a2]      + Oa[mf][nf][2] * inv1;
            out[a2 + NN] = x[a2 + NN] + Oa[mf][nf][3] * inv1;
        }
    }
}

// ---------------------------------------------------------------------------
// Launch
// ---------------------------------------------------------------------------
extern "C" void kernel_launch(void* const* d_in, const int* in_sizes, int n_in,
                              void* d_out, int out_size) {
    const float* x  = (const float*)d_in[0];
    const float* pv = (const float*)d_in[1];
    const float* pg = (const float*)d_in[2];
    const float* pb = (const float*)d_in[3];
    float* out = (float*)d_out;

    convert_x<<<(BB * CC * NN) / (256 * 4), 256>>>(x);
    prep_w<<<O3 / 8, 256>>>(pv, pg);

    cudaFuncSetAttribute(proj_mma,
                         cudaFuncAttributeMaxDynamicSharedMemorySize, PROJ_SMEM);
    dim3 pgrid(NN / 128, O3 / 128, BB);
    proj_mma<<<pgrid, 256, PROJ_SMEM>>>(pb);

    cudaFuncSetAttribute(attn_mma,
                         cudaFuncAttributeMaxDynamicSharedMemorySize, ATTN_SMEM);
    dim3 agrid(NN / 128, BB * HEADS);
    attn_mma<<<agrid, 256, ATTN_SMEM>>>(x, out);
}

// round 14
// speedup vs baseline: 5.6511x; 1.0669x over previous
#include <cuda_runtime.h>
#include <cuda_fp16.h>
#include <math.h>

// Problem constants
#define CC    512      // channels
#define O3    1536     // 3*C
#define NN    1024     // H*W
#define BB    8        // batch
#define DIM   64       // head dim
#define HEADS 8

// ---------------------------------------------------------------------------
// Scratch
// ---------------------------------------------------------------------------
__device__ __half g_wh[(size_t)O3 * CC];              // fp16 weight-normed W
__device__ __half g_xh[(size_t)BB * CC * NN];         // fp16 x
__device__ __half g_qkvh[(size_t)BB * O3 * NN];       // 25 MB fp16 qkv

// ---------------------------------------------------------------------------
// helpers
// ---------------------------------------------------------------------------
__device__ __forceinline__ unsigned smaddr(const void* p) {
    return (unsigned)__cvta_generic_to_shared(p);
}
__device__ __forceinline__ void cpa16(unsigned dst, const void* src) {
    asm volatile("cp.async.cg.shared.global [%0], [%1], 16;" :: "r"(dst), "l"(src));
}
__device__ __forceinline__ void cp_commit() {
    asm volatile("cp.async.commit_group;");
}
template<int N> __device__ __forceinline__ void cp_wait() {
    asm volatile("cp.async.wait_group %0;" :: "n"(N));
}
__device__ __forceinline__ void mma16h(float* c, const unsigned* a, const unsigned* b) {
    asm volatile(
        "mma.sync.aligned.m16n8k16.row.col.f32.f16.f16.f32 "
        "{%0,%1,%2,%3}, {%4,%5,%6,%7}, {%8,%9}, {%0,%1,%2,%3};\n"
        : "+f"(c[0]), "+f"(c[1]), "+f"(c[2]), "+f"(c[3])
        : "r"(a[0]), "r"(a[1]), "r"(a[2]), "r"(a[3]), "r"(b[0]), "r"(b[1]));
}
__device__ __forceinline__ void ldsm4(unsigned* r, unsigned a) {
    asm volatile("ldmatrix.sync.aligned.m8n8.x4.shared.b16 {%0,%1,%2,%3}, [%4];"
        : "=r"(r[0]), "=r"(r[1]), "=r"(r[2]), "=r"(r[3]) : "r"(a));
}
__device__ __forceinline__ void ldsm4t(unsigned* r, unsigned a) {
    asm volatile("ldmatrix.sync.aligned.m8n8.x4.trans.shared.b16 {%0,%1,%2,%3}, [%4];"
        : "=r"(r[0]), "=r"(r[1]), "=r"(r[2]), "=r"(r[3]) : "r"(a));
}
__device__ __forceinline__ unsigned h2exp2(unsigned x) {
    unsigned r;
    asm("ex2.approx.f16x2 %0, %1;" : "=r"(r) : "r"(x));
    return r;
}

// ---------------------------------------------------------------------------
// Kernel 0: x -> fp16
// ---------------------------------------------------------------------------
__global__ void convert_x(const float* __restrict__ x) {
    size_t i = ((size_t)blockIdx.x * 256 + threadIdx.x) * 4;
    float4 v = *(const float4*)(x + i);
    *(__half2*)(g_xh + i)     = __floats2half2_rn(v.x, v.y);
    *(__half2*)(g_xh + i + 2) = __floats2half2_rn(v.z, v.w);
}

// ---------------------------------------------------------------------------
// Kernel 1: w[o][c] = fp16( proj_g[o]/||proj_v[o,:]|| * proj_v[o][c] )
// ---------------------------------------------------------------------------
__global__ void prep_w(const float* __restrict__ pv,
                       const float* __restrict__ pg) {
    int o = blockIdx.x * 8 + (threadIdx.x >> 5);
    int lane = threadIdx.x & 31;
    const float* row = pv + (size_t)o * CC;
    float s = 0.f;
    #pragma unroll 4
    for (int i = lane; i < CC; i += 32) { float v = row[i]; s += v * v; }
    #pragma unroll
    for (int off = 16; off; off >>= 1) s += __shfl_xor_sync(0xffffffffu, s, off);
    float sc = pg[o] / sqrtf(s);
    #pragma unroll 4
    for (int c = lane * 2; c < CC; c += 64)
        *(__half2*)(g_wh + (size_t)o * CC + c) =
            __floats2half2_rn(row[c] * sc, row[c + 1] * sc);
}

// ---------------------------------------------------------------------------
// Kernel 2: qkv = w @ x + b  (fp16 m16n8k16 mma, ldmatrix, 4-stage cp.async).
// CTA tile 128x128, k-tile 32, 8 warps 2m x 4n (64x32 warp tiles).
// B-fragments batched via ldsm4t (2 n8 tiles per instruction).
// ---------------------------------------------------------------------------
#define PK 32
#define WTS 40                           // W tile stride (halves)
#define XTS 136                          // X tile stride (halves)
#define W_HALFS (128 * WTS)
#define X_HALFS (PK * XTS)
#define STG_B ((W_HALFS + X_HALFS) * 2)
#define NSTG 4
#define PROJ_SMEM (NSTG * STG_B)         // 75,776 B

__global__ __launch_bounds__(256, 2)
void proj_mma(const float* __restrict__ pb) {
    extern __shared__ char psmc[];

    const int b  = blockIdx.z;
    const int bm = blockIdx.y * 128;
    const int bn = blockIdx.x * 128;
    const __half* xb = g_xh + (size_t)b * CC * NN;
    __half* outp = g_qkvh + (size_t)b * O3 * NN;

    const int t    = threadIdx.x;
    const int w    = t >> 5;
    const int lane = t & 31;
    const int g    = lane >> 2;
    const int t4   = lane & 3;
    const int moff = (w & 1) * 64;
    const int noff = (w >> 1) * 32;

    const unsigned base_u = smaddr(psmc);
    const int rA = (lane & 8) + (lane & 7);        // ldsm4 A rows
    const int cA = (lane & 16) >> 1;               // ldsm4 A col offset
    const int rB = lane & 15;                      // ldsm4t B rows
    const int cB = (lane & 16) >> 1;               // ldsm4t B col offset

    float c[4][4][4];
    #pragma unroll
    for (int mf = 0; mf < 4; mf++)
        #pragma unroll
        for (int nf = 0; nf < 4; nf++)
            #pragma unroll
            for (int i = 0; i < 4; i++) c[mf][nf][i] = 0.f;

    auto load_stage = [&](int stg, int kt) {
        unsigned sd = base_u + stg * STG_B;
        int k0 = kt * PK;
        #pragma unroll
        for (int i = 0; i < 2; i++) {
            int idx = t + i * 256;
            int r = idx >> 2, c8 = idx & 3;
            cpa16(sd + (unsigned)(r * WTS + c8 * 8) * 2,
                  g_wh + (size_t)(bm + r) * CC + k0 + c8 * 8);
        }
        unsigned xd = sd + W_HALFS * 2;
        #pragma unroll
        for (int i = 0; i < 2; i++) {
            int idx = t + i * 256;
            int r = idx >> 4, c8 = idx & 15;
            cpa16(xd + (unsigned)(r * XTS + c8 * 8) * 2,
                  xb + (size_t)(k0 + r) * NN + bn + c8 * 8);
        }
    };

    load_stage(0, 0); cp_commit();
    load_stage(1, 1); cp_commit();
    load_stage(2, 2); cp_commit();

    for (int kt = 0; kt < 16; kt++) {
        cp_wait<2>();
        __syncthreads();
        if (kt + 3 < 16) load_stage((kt + 3) % NSTG, kt + 3);
        cp_commit();

        const unsigned wcur = base_u + (kt % NSTG) * STG_B;
        const unsigned xcur = wcur + W_HALFS * 2;

        #pragma unroll
        for (int ks = 0; ks < 2; ks++) {
            const int koff = ks * 16;
            unsigned a[4][4], bq[4][2];
            #pragma unroll
            for (int mf = 0; mf < 4; mf++)
                ldsm4(a[mf], wcur +
                    (unsigned)(((moff + mf * 16 + rA) * WTS + koff + cA) * 2));
            #pragma unroll
            for (int j = 0; j < 2; j++) {
                unsigned r4[4];
                ldsm4t(r4, xcur +
                    (unsigned)(((koff + rB) * XTS + noff + j * 16 + cB) * 2));
                bq[2 * j][0] = r4[0]; bq[2 * j][1] = r4[1];
                bq[2 * j + 1][0] = r4[2]; bq[2 * j + 1][1] = r4[3];
            }
            #pragma unroll
            for (int mf = 0; mf < 4; mf++)
                #pragma unroll
                for (int nf = 0; nf < 4; nf++)
                    mma16h(c[mf][nf], a[mf], bq[nf]);
        }
    }

    #pragma unroll
    for (int mf = 0; mf < 4; mf++) {
        int o = bm + moff + mf * 16 + g;
        float bias0 = pb[o], bias1 = pb[o + 8];
        #pragma unroll
        for (int nf = 0; nf < 4; nf++) {
            int n = bn + noff + nf * 8 + 2 * t4;
            *(__half2*)(outp + (size_t)o * NN + n) =
                __floats2half2_rn(c[mf][nf][0] + bias0, c[mf][nf][1] + bias0);
            *(__half2*)(outp + (size_t)(o + 8) * NN + n) =
                __floats2half2_rn(c[mf][nf][2] + bias1, c[mf][nf][3] + bias1);
        }
    }
}

// ---------------------------------------------------------------------------
// Kernel 3: flash attention, register-fragment P (no P SMEM round trip).
// 8 warps = 4 q-quarters x 2 k-halves. Each warp: S(32q x 64k) -> softmax in
// regs -> GEMM1 C-frags become GEMM2 A-frags directly. Partial O per k-half;
// single cross-half reduction in the epilogue. Q A-frags preloaded to regs.
// ---------------------------------------------------------------------------
#define STR 136          // halves per row
#define KTILE_B 17408    // 64*136*2
#define QS_OFF   0
#define KS_OFF   17408
#define VS_OFF   52224   // after 2 K buffers
#define PMAX_OFF 69632   // float[2][128]
#define PSUM_OFF 70656   // float[2][128]
#define ATTN_SMEM 71680
#define ORED_STR 72      // epilogue O-reduce row stride (floats), reuses smem@0

__global__ __launch_bounds__(256, 1)
void attn_mma(const float* __restrict__ x, float* __restrict__ out) {
    extern __shared__ char smc[];
    float* pmax = (float*)(smc + PMAX_OFF);
    float* psum = (float*)(smc + PSUM_OFF);
    float* Ored = (float*)(smc);              // [128][ORED_STR] after mainloop

    const int t    = threadIdx.x;
    const int w    = t >> 5;
    const int lane = t & 31;
    const int g    = lane >> 2;
    const int t4   = lane & 3;
    const int bh   = blockIdx.y;
    const int b    = bh >> 3, h = bh & 7;
    const int q0   = blockIdx.x * 128;

    const int qw    = w >> 1;          // q-quarter (0..3)
    const int hw    = w & 1;           // k-half (0..1)
    const int m1off = qw * 32;
    const int n1off = hw * 64;

    const __half* Qg = g_qkvh + ((size_t)b * O3 + h * DIM) * NN;
    const __half* Kg = Qg + (size_t)CC * NN;
    const __half* Vg = Qg + (size_t)2 * CC * NN;

    const unsigned qs_u = smaddr(smc + QS_OFF);
    const unsigned ks_u = smaddr(smc + KS_OFF);
    const unsigned vs_u = smaddr(smc + VS_OFF);

    // ldmatrix per-lane address components
    const int rA = ((lane & 16) >> 1) + (lane & 7);  // A-style x4 / GEMM2 B x4
    const int cA = lane & 8;
    const int rB = lane & 15;                        // GEMM1 B x4t
    const int cB = (lane & 16) >> 1;

    const int ld_d  = t >> 4;
    const int ld_c8 = t & 15;

    // Prologue: async Q tile + K(0)
    #pragma unroll
    for (int i = 0; i < 4; i++) {
        int d = ld_d + i * 16;
        cpa16(qs_u + (unsigned)(d * STR + ld_c8 * 8) * 2,
              Qg + (size_t)d * NN + q0 + ld_c8 * 8);
        cpa16(ks_u + (unsigned)(d * STR + ld_c8 * 8) * 2,
              Kg + (size_t)d * NN + 0 + ld_c8 * 8);
    }
    cp_commit();
    cp_wait<0>();
    __syncthreads();

    // Preload Q A-fragments (2 m16 tiles x 4 k16 chunks)
    unsigned qf[2][4][4];
    #pragma unroll
    for (int mf = 0; mf < 2; mf++)
        #pragma unroll
        for (int ks = 0; ks < 4; ks++)
            ldsm4t(qf[mf][ks], qs_u +
                (unsigned)(((ks * 16 + rA) * STR + m1off + mf * 16 + cA) * 2));

    float Oa[2][8][4];
    #pragma unroll
    for (int mf = 0; mf < 2; mf++)
        #pragma unroll
        for (int nf = 0; nf < 8; nf++)
            #pragma unroll
            for (int i = 0; i < 4; i++) Oa[mf][nf][i] = 0.f;

    float lm[2][2], ll[2][2];
    #pragma unroll
    for (int mf = 0; mf < 2; mf++) {
        lm[mf][0] = lm[mf][1] = -3.0e38f;
        ll[mf][0] = ll[mf][1] = 0.f;
    }

    const float CE = 0.18033688f;   // 0.125 * log2(e)

    for (int it = 0; it < 8; it++) {
        const int k0 = it * 128;
        if (it) {
            cp_wait<0>();
            __syncthreads();          // K(it) visible; Vs free (GEMM2 done)
        }

        // issue V(it)
        #pragma unroll
        for (int i = 0; i < 4; i++) {
            int d = ld_d + i * 16;
            cpa16(vs_u + (unsigned)(d * STR + ld_c8 * 8) * 2,
                  Vg + (size_t)d * NN + k0 + ld_c8 * 8);
        }
        cp_commit();

        const unsigned ks_cur = ks_u + (unsigned)(it & 1) * KTILE_B;

        // ---- GEMM1: S(32q x 64k) = Q^T K over warp's k-half ----
        float c1[2][8][4];
        #pragma unroll
        for (int mf = 0; mf < 2; mf++)
            #pragma unroll
            for (int nf = 0; nf < 8; nf++)
                #pragma unroll
                for (int i = 0; i < 4; i++) c1[mf][nf][i] = 0.f;

        #pragma unroll
        for (int ks = 0; ks < 4; ks++) {
            const int koff = ks * 16;
            unsigned bq[8][2];
            #pragma unroll
            for (int j = 0; j < 4; j++) {
                unsigned r4[4];
                ldsm4t(r4, ks_cur +
                    (unsigned)(((koff + rB) * STR + n1off + j * 16 + cB) * 2));
                bq[2 * j][0] = r4[0]; bq[2 * j][1] = r4[1];
                bq[2 * j + 1][0] = r4[2]; bq[2 * j + 1][1] = r4[3];
            }
            #pragma unroll
            for (int mf = 0; mf < 2; mf++)
                #pragma unroll
                for (int nf = 0; nf < 8; nf++)
                    mma16h(c1[mf][nf], qf[mf][ks], bq[nf]);
        }

        // prefetch K(it+1)
        if (it < 7) {
            const unsigned ks_nxt = ks_u + (unsigned)((it + 1) & 1) * KTILE_B;
            #pragma unroll
            for (int i = 0; i < 4; i++) {
                int d = ld_d + i * 16;
                cpa16(ks_nxt + (unsigned)(d * STR + ld_c8 * 8) * 2,
                      Kg + (size_t)d * NN + (k0 + 128) + ld_c8 * 8);
            }
        }
        cp_commit();

        // ---- phase 1: per-warp row maxima over 64 cols -> pmax[hw] ----
        #pragma unroll
        for (int mf = 0; mf < 2; mf++) {
            float m0 = -3.0e38f, m1 = -3.0e38f;
            #pragma unroll
            for (int nf = 0; nf < 8; nf++) {
                m0 = fmaxf(m0, fmaxf(c1[mf][nf][0], c1[mf][nf][1]));
                m1 = fmaxf(m1, fmaxf(c1[mf][nf][2], c1[mf][nf][3]));
            }
            m0 = fmaxf(m0, __shfl_xor_sync(0xffffffffu, m0, 1));
            m0 = fmaxf(m0, __shfl_xor_sync(0xffffffffu, m0, 2));
            m1 = fmaxf(m1, __shfl_xor_sync(0xffffffffu, m1, 1));
            m1 = fmaxf(m1, __shfl_xor_sync(0xffffffffu, m1, 2));
            if (t4 == 0) {
                int r = m1off + mf * 16 + g;
                pmax[hw * 128 + r]     = m0;
                pmax[hw * 128 + r + 8] = m1;
            }
        }
        __syncthreads();

        // ---- phase 2: exp (f16x2) -> P A-fragments in regs; psum ----
        unsigned ph[2][8][2];
        #pragma unroll
        for (int mf = 0; mf < 2; mf++) {
            int r0 = m1off + mf * 16 + g;
            int r1 = r0 + 8;
            float nm0 = fmaxf(fmaxf(pmax[r0], pmax[128 + r0]), lm[mf][0]);
            float nm1 = fmaxf(fmaxf(pmax[r1], pmax[128 + r1]), lm[mf][1]);
            float s0 = 0.f, s1 = 0.f;
            #pragma unroll
            for (int nf = 0; nf < 8; nf++) {
                __half2 ha = __floats2half2_rn((c1[mf][nf][0] - nm0) * CE,
                                               (c1[mf][nf][1] - nm0) * CE);
                __half2 hb = __floats2half2_rn((c1[mf][nf][2] - nm1) * CE,
                                               (c1[mf][nf][3] - nm1) * CE);
                unsigned pa = h2exp2(*(unsigned*)&ha);
                unsigned pc = h2exp2(*(unsigned*)&hb);
                float2 fa = __half22float2(*(__half2*)&pa);
                float2 fc = __half22float2(*(__half2*)&pc);
                s0 += fa.x + fa.y;
                s1 += fc.x + fc.y;
                ph[mf][nf][0] = pa;   // rows g   (a0 / a2 source)
                ph[mf][nf][1] = pc;   // rows g+8 (a1 / a3 source)
            }
            s0 += __shfl_xor_sync(0xffffffffu, s0, 1);
            s0 += __shfl_xor_sync(0xffffffffu, s0, 2);
            s1 += __shfl_xor_sync(0xffffffffu, s1, 1);
            s1 += __shfl_xor_sync(0xffffffffu, s1, 2);
            if (t4 == 0) {
                psum[hw * 128 + r0] = s0;
                psum[hw * 128 + r1] = s1;
            }
        }
        cp_wait<1>();                 // V(it) done (K(it+1) may still fly)
        __syncthreads();              // psum + Vs visible

        // ---- row-state update + O rescale ----
        #pragma unroll
        for (int mf = 0; mf < 2; mf++) {
            int r0 = m1off + mf * 16 + g;
            int r1 = r0 + 8;
            float nm0 = fmaxf(fmaxf(pmax[r0], pmax[128 + r0]), lm[mf][0]);
            float nm1 = fmaxf(fmaxf(pmax[r1], pmax[128 + r1]), lm[mf][1]);
            float sum0 = psum[r0] + psum[128 + r0];
            float sum1 = psum[r1] + psum[128 + r1];
            float f0 = exp2f((lm[mf][0] - nm0) * CE);
            float f1 = exp2f((lm[mf][1] - nm1) * CE);
            ll[mf][0] = ll[mf][0] * f0 + sum0;
            ll[mf][1] = ll[mf][1] * f1 + sum1;
            lm[mf][0] = nm0;
            lm[mf][1] = nm1;
            #pragma unroll
            for (int nf = 0; nf < 8; nf++) {
                Oa[mf][nf][0] *= f0; Oa[mf][nf][1] *= f0;
                Oa[mf][nf][2] *= f1; Oa[mf][nf][3] *= f1;
            }
        }

        // ---- GEMM2: O(32q x 64d) += P V^T over warp's k-half ----
        #pragma unroll
        for (int ks = 0; ks < 4; ks++) {
            const int koff = ks * 16;
            unsigned bv[8][2];
            #pragma unroll
            for (int j = 0; j < 4; j++) {
                unsigned r4[4];
                ldsm4(r4, vs_u +
                    (unsigned)(((j * 16 + rA) * STR + n1off + koff + cA) * 2));
                bv[2 * j][0] = r4[0]; bv[2 * j][1] = r4[1];
                bv[2 * j + 1][0] = r4[2]; bv[2 * j + 1][1] = r4[3];
            }
            #pragma unroll
            for (int mf = 0; mf < 2; mf++) {
                unsigned af[4] = { ph[mf][2 * ks][0], ph[mf][2 * ks][1],
                                   ph[mf][2 * ks + 1][0], ph[mf][2 * ks + 1][1] };
                #pragma unroll
                for (int nf = 0; nf < 8; nf++)
                    mma16h(Oa[mf][nf], af, bv[nf]);
            }
        }
    }

    // ---- epilogue: cross-k-half O reduction + residual + store ----
    __syncthreads();                  // mainloop SMEM dead; reuse as Ored
    if (hw == 1) {
        #pragma unroll
        for (int mf = 0; mf < 2; mf++) {
            int r0 = m1off + mf * 16 + g;
            #pragma unroll
            for (int nf = 0; nf < 8; nf++) {
                int col = nf * 8 + 2 * t4;
                *(float2*)(Ored + r0 * ORED_STR + col) =
                    make_float2(Oa[mf][nf][0], Oa[mf][nf][1]);
                *(float2*)(Ored + (r0 + 8) * ORED_STR + col) =
                    make_float2(Oa[mf][nf][2], Oa[mf][nf][3]);
            }
        }
    }
    __syncthreads();
    if (hw == 0) {
        const size_t base = ((size_t)b * CC + h * DIM) * NN + q0;
        #pragma unroll
        for (int mf = 0; mf < 2; mf++) {
            int q = m1off + mf * 16 + g;
            float inv0 = 1.f / ll[mf][0];
            float inv1 = 1.f / ll[mf][1];
            #pragma unroll
            for (int nf = 0; nf < 8; nf++) {
                int col = nf * 8 + 2 * t4;
                float2 o0 = *(const float2*)(Ored + q * ORED_STR + col);
                float2 o1 = *(const float2*)(Ored + (q + 8) * ORED_STR + col);
                size_t a0 = base + (size_t)col * NN + q;
                out[a0]      = x[a0]      + (Oa[mf][nf][0] + o0.x) * inv0;
                out[a0 + NN] = x[a0 + NN] + (Oa[mf][nf][1] + o0.y) * inv0;
                size_t a2 = a0 + 8;
                out[a2]      = x[a2]      + (Oa[mf][nf][2] + o1.x) * inv1;
                out[a2 + NN] = x[a2 + NN] + (Oa[mf][nf][3] + o1.y) * inv1;
            }
        }
    }
}

// ---------------------------------------------------------------------------
// Launch
// ---------------------------------------------------------------------------
extern "C" void kernel_launch(void* const* d_in, const int* in_sizes, int n_in,
                              void* d_out, int out_size) {
    const float* x  = (const float*)d_in[0];
    const float* pv = (const float*)d_in[1];
    const float* pg = (const float*)d_in[2];
    const float* pb = (const float*)d_in[3];
    float* out = (float*)d_out;

    convert_x<<<(BB * CC * NN) / (256 * 4), 256>>>(x);
    prep_w<<<O3 / 8, 256>>>(pv, pg);

    cudaFuncSetAttribute(proj_mma,
                         cudaFuncAttributeMaxDynamicSharedMemorySize, PROJ_SMEM);
    dim3 pgrid(NN / 128, O3 / 128, BB);
    proj_mma<<<pgrid, 256, PROJ_SMEM>>>(pb);

    cudaFuncSetAttribute(attn_mma,
                         cudaFuncAttributeMaxDynamicSharedMemorySize, ATTN_SMEM);
    dim3 agrid(NN / 128, BB * HEADS);
    attn_mma<<<agrid, 256, ATTN_SMEM>>>(x, out);
}

// round 16
// speedup vs baseline: 6.2714x; 1.1098x over previous
#include <cuda_runtime.h>
#include <cuda_fp16.h>
#include <math.h>

// Problem constants
#define CC    512      // channels
#define O3    1536     // 3*C
#define NN    1024     // H*W
#define BB    8        // batch
#define DIM   64       // head dim
#define HEADS 8

// ---------------------------------------------------------------------------
// Scratch
// ---------------------------------------------------------------------------
__device__ __half g_wh[(size_t)O3 * CC];              // fp16 weight-normed W
__device__ __half g_xh[(size_t)BB * CC * NN];         // fp16 x
__device__ __half g_qkvh[(size_t)BB * O3 * NN];       // 25 MB fp16 qkv

// ---------------------------------------------------------------------------
// helpers
// ---------------------------------------------------------------------------
__device__ __forceinline__ unsigned smaddr(const void* p) {
    return (unsigned)__cvta_generic_to_shared(p);
}
__device__ __forceinline__ void cpa16(unsigned dst, const void* src) {
    asm volatile("cp.async.cg.shared.global [%0], [%1], 16;" :: "r"(dst), "l"(src));
}
__device__ __forceinline__ void cp_commit() {
    asm volatile("cp.async.commit_group;");
}
template<int N> __device__ __forceinline__ void cp_wait() {
    asm volatile("cp.async.wait_group %0;" :: "n"(N));
}
__device__ __forceinline__ void mma16h(float* c, const unsigned* a, const unsigned* b) {
    asm volatile(
        "mma.sync.aligned.m16n8k16.row.col.f32.f16.f16.f32 "
        "{%0,%1,%2,%3}, {%4,%5,%6,%7}, {%8,%9}, {%0,%1,%2,%3};\n"
        : "+f"(c[0]), "+f"(c[1]), "+f"(c[2]), "+f"(c[3])
        : "r"(a[0]), "r"(a[1]), "r"(a[2]), "r"(a[3]), "r"(b[0]), "r"(b[1]));
}
__device__ __forceinline__ void ldsm4(unsigned* r, unsigned a) {
    asm volatile("ldmatrix.sync.aligned.m8n8.x4.shared.b16 {%0,%1,%2,%3}, [%4];"
        : "=r"(r[0]), "=r"(r[1]), "=r"(r[2]), "=r"(r[3]) : "r"(a));
}
__device__ __forceinline__ void ldsm4t(unsigned* r, unsigned a) {
    asm volatile("ldmatrix.sync.aligned.m8n8.x4.trans.shared.b16 {%0,%1,%2,%3}, [%4];"
        : "=r"(r[0]), "=r"(r[1]), "=r"(r[2]), "=r"(r[3]) : "r"(a));
}
__device__ __forceinline__ unsigned h2exp2(unsigned x) {
    unsigned r;
    asm("ex2.approx.f16x2 %0, %1;" : "=r"(r) : "r"(x));
    return r;
}

// ---------------------------------------------------------------------------
// Kernel 0: x -> fp16
// ---------------------------------------------------------------------------
__global__ void convert_x(const float* __restrict__ x) {
    size_t i = ((size_t)blockIdx.x * 256 + threadIdx.x) * 4;
    float4 v = *(const float4*)(x + i);
    *(__half2*)(g_xh + i)     = __floats2half2_rn(v.x, v.y);
    *(__half2*)(g_xh + i + 2) = __floats2half2_rn(v.z, v.w);
}

// ---------------------------------------------------------------------------
// Kernel 1: w[o][c] = fp16( proj_g[o]/||proj_v[o,:]|| * proj_v[o][c] )
// ---------------------------------------------------------------------------
__global__ void prep_w(const float* __restrict__ pv,
                       const float* __restrict__ pg) {
    int o = blockIdx.x * 8 + (threadIdx.x >> 5);
    int lane = threadIdx.x & 31;
    const float* row = pv + (size_t)o * CC;
    float s = 0.f;
    #pragma unroll 4
    for (int i = lane; i < CC; i += 32) { float v = row[i]; s += v * v; }
    #pragma unroll
    for (int off = 16; off; off >>= 1) s += __shfl_xor_sync(0xffffffffu, s, off);
    float sc = pg[o] / sqrtf(s);
    #pragma unroll 4
    for (int c = lane * 2; c < CC; c += 64)
        *(__half2*)(g_wh + (size_t)o * CC + c) =
            __floats2half2_rn(row[c] * sc, row[c + 1] * sc);
}

// ---------------------------------------------------------------------------
// Kernel 2: qkv = w @ x + b  (fp16 m16n8k16 mma, ldmatrix, 4-stage cp.async).
// Unchanged from round 14 (control).
// ---------------------------------------------------------------------------
#define PK 32
#define WTS 40
#define XTS 136
#define W_HALFS (128 * WTS)
#define X_HALFS (PK * XTS)
#define STG_B ((W_HALFS + X_HALFS) * 2)
#define NSTG 4
#define PROJ_SMEM (NSTG * STG_B)         // 75,776 B

__global__ __launch_bounds__(256, 2)
void proj_mma(const float* __restrict__ pb) {
    extern __shared__ char psmc[];

    const int b  = blockIdx.z;
    const int bm = blockIdx.y * 128;
    const int bn = blockIdx.x * 128;
    const __half* xb = g_xh + (size_t)b * CC * NN;
    __half* outp = g_qkvh + (size_t)b * O3 * NN;

    const int t    = threadIdx.x;
    const int w    = t >> 5;
    const int lane = t & 31;
    const int g    = lane >> 2;
    const int t4   = lane & 3;
    const int moff = (w & 1) * 64;
    const int noff = (w >> 1) * 32;

    const unsigned base_u = smaddr(psmc);
    const int rA = (lane & 8) + (lane & 7);
    const int cA = (lane & 16) >> 1;
    const int rB = lane & 15;
    const int cB = (lane & 16) >> 1;

    float c[4][4][4];
    #pragma unroll
    for (int mf = 0; mf < 4; mf++)
        #pragma unroll
        for (int nf = 0; nf < 4; nf++)
            #pragma unroll
            for (int i = 0; i < 4; i++) c[mf][nf][i] = 0.f;

    auto load_stage = [&](int stg, int kt) {
        unsigned sd = base_u + stg * STG_B;
        int k0 = kt * PK;
        #pragma unroll
        for (int i = 0; i < 2; i++) {
            int idx = t + i * 256;
            int r = idx >> 2, c8 = idx & 3;
            cpa16(sd + (unsigned)(r * WTS + c8 * 8) * 2,
                  g_wh + (size_t)(bm + r) * CC + k0 + c8 * 8);
        }
        unsigned xd = sd + W_HALFS * 2;
        #pragma unroll
        for (int i = 0; i < 2; i++) {
            int idx = t + i * 256;
            int r = idx >> 4, c8 = idx & 15;
            cpa16(xd + (unsigned)(r * XTS + c8 * 8) * 2,
                  xb + (size_t)(k0 + r) * NN + bn + c8 * 8);
        }
    };

    load_stage(0, 0); cp_commit();
    load_stage(1, 1); cp_commit();
    load_stage(2, 2); cp_commit();

    for (int kt = 0; kt < 16; kt++) {
        cp_wait<2>();
        __syncthreads();
        if (kt + 3 < 16) load_stage((kt + 3) % NSTG, kt + 3);
        cp_commit();

        const unsigned wcur = base_u + (kt % NSTG) * STG_B;
        const unsigned xcur = wcur + W_HALFS * 2;

        #pragma unroll
        for (int ks = 0; ks < 2; ks++) {
            const int koff = ks * 16;
            unsigned a[4][4], bq[4][2];
            #pragma unroll
            for (int mf = 0; mf < 4; mf++)
                ldsm4(a[mf], wcur +
                    (unsigned)(((moff + mf * 16 + rA) * WTS + koff + cA) * 2));
            #pragma unroll
            for (int j = 0; j < 2; j++) {
                unsigned r4[4];
                ldsm4t(r4, xcur +
                    (unsigned)(((koff + rB) * XTS + noff + j * 16 + cB) * 2));
                bq[2 * j][0] = r4[0]; bq[2 * j][1] = r4[1];
                bq[2 * j + 1][0] = r4[2]; bq[2 * j + 1][1] = r4[3];
            }
            #pragma unroll
            for (int mf = 0; mf < 4; mf++)
                #pragma unroll
                for (int nf = 0; nf < 4; nf++)
                    mma16h(c[mf][nf], a[mf], bq[nf]);
        }
    }

    #pragma unroll
    for (int mf = 0; mf < 4; mf++) {
        int o = bm + moff + mf * 16 + g;
        float bias0 = pb[o], bias1 = pb[o + 8];
        #pragma unroll
        for (int nf = 0; nf < 4; nf++) {
            int n = bn + noff + nf * 8 + 2 * t4;
            *(__half2*)(outp + (size_t)o * NN + n) =
                __floats2half2_rn(c[mf][nf][0] + bias0, c[mf][nf][1] + bias0);
            *(__half2*)(outp + (size_t)(o + 8) * NN + n) =
                __floats2half2_rn(c[mf][nf][2] + bias1, c[mf][nf][3] + bias1);
        }
    }
}

// ---------------------------------------------------------------------------
// Kernel 3: flash attention, warp-autonomous softmax.
// 8 warps = 8 q-stripes (16 rows each); each warp owns the FULL 128-k range.
// Softmax entirely warp-local (t4 shfls only) -> 2 barriers/iter, zero
// softmax SMEM, warps drift so HMMA/MUFU/FMA overlap across warps.
// Partial-O reduction eliminated (each warp owns all k): direct epilogue.
// ---------------------------------------------------------------------------
#define STR 136          // halves per row
#define KTILE_B 17408    // 64*136*2
#define QS_OFF   0
#define KS_OFF   17408
#define VS_OFF   52224   // after 2 K buffers
#define ATTN_SMEM 69632

__global__ __launch_bounds__(256, 1)
void attn_mma(const float* __restrict__ x, float* __restrict__ out) {
    extern __shared__ char smc[];

    const int t    = threadIdx.x;
    const int w    = t >> 5;
    const int lane = t & 31;
    const int g    = lane >> 2;
    const int t4   = lane & 3;
    const int bh   = blockIdx.y;
    const int b    = bh >> 3, h = bh & 7;
    const int q0   = blockIdx.x * 128;

    const int m1off = w * 16;          // warp's q-stripe

    const __half* Qg = g_qkvh + ((size_t)b * O3 + h * DIM) * NN;
    const __half* Kg = Qg + (size_t)CC * NN;
    const __half* Vg = Qg + (size_t)2 * CC * NN;

    const unsigned qs_u = smaddr(smc + QS_OFF);
    const unsigned ks_u = smaddr(smc + KS_OFF);
    const unsigned vs_u = smaddr(smc + VS_OFF);

    // ldmatrix per-lane address components
    const int rA = ((lane & 16) >> 1) + (lane & 7);  // x4 A-style rows
    const int cA = lane & 8;                         // x4 A-style col offset
    const int rB = lane & 15;                        // x4t B rows
    const int cB = (lane & 16) >> 1;                 // x4t B col offset

    const int ld_d  = t >> 4;
    const int ld_c8 = t & 15;

    // Prologue: async Q tile + K(0)
    #pragma unroll
    for (int i = 0; i < 4; i++) {
        int d = ld_d + i * 16;
        cpa16(qs_u + (unsigned)(d * STR + ld_c8 * 8) * 2,
              Qg + (size_t)d * NN + q0 + ld_c8 * 8);
        cpa16(ks_u + (unsigned)(d * STR + ld_c8 * 8) * 2,
              Kg + (size_t)d * NN + 0 + ld_c8 * 8);
    }
    cp_commit();
    cp_wait<0>();
    __syncthreads();

    // Preload warp's Q A-fragments: m16 x 4 k16 chunks (16 regs)
    unsigned qf[4][4];
    #pragma unroll
    for (int ks = 0; ks < 4; ks++)
        ldsm4t(qf[ks], qs_u +
            (unsigned)(((ks * 16 + rA) * STR + m1off + cA) * 2));

    float Oa[8][4];
    #pragma unroll
    for (int nf = 0; nf < 8; nf++)
        #pragma unroll
        for (int i = 0; i < 4; i++) Oa[nf][i] = 0.f;

    float lm0 = -3.0e38f, lm1 = -3.0e38f, ll0 = 0.f, ll1 = 0.f;

    const float CE = 0.18033688f;   // 0.125 * log2(e)

    for (int it = 0; it < 8; it++) {
        const int k0 = it * 128;
        if (it) {
            cp_wait<0>();
            __syncthreads();          // [B1] K(it) visible; Vs free
        }

        // issue V(it)
        #pragma unroll
        for (int i = 0; i < 4; i++) {
            int d = ld_d + i * 16;
            cpa16(vs_u + (unsigned)(d * STR + ld_c8 * 8) * 2,
                  Vg + (size_t)d * NN + k0 + ld_c8 * 8);
        }
        cp_commit();

        const unsigned ks_cur = ks_u + (unsigned)(it & 1) * KTILE_B;

        // ---- GEMM1: S(16q x 128k) = Q^T K ----
        float c1[16][4];
        #pragma unroll
        for (int nf = 0; nf < 16; nf++)
            #pragma unroll
            for (int i = 0; i < 4; i++) c1[nf][i] = 0.f;

        #pragma unroll
        for (int ks = 0; ks < 4; ks++) {
            const int koff = ks * 16;
            unsigned bq[16][2];
            #pragma unroll
            for (int j = 0; j < 8; j++) {
                unsigned r4[4];
                ldsm4t(r4, ks_cur +
                    (unsigned)(((koff + rB) * STR + j * 16 + cB) * 2));
                bq[2 * j][0] = r4[0]; bq[2 * j][1] = r4[1];
                bq[2 * j + 1][0] = r4[2]; bq[2 * j + 1][1] = r4[3];
            }
            #pragma unroll
            for (int nf = 0; nf < 16; nf++)
                mma16h(c1[nf], qf[ks], bq[nf]);
        }

        // prefetch K(it+1) (all warps finished reading that buffer pre-B1)
        if (it < 7) {
            const unsigned ks_nxt = ks_u + (unsigned)((it + 1) & 1) * KTILE_B;
            #pragma unroll
            for (int i = 0; i < 4; i++) {
                int d = ld_d + i * 16;
                cpa16(ks_nxt + (unsigned)(d * STR + ld_c8 * 8) * 2,
                      Kg + (size_t)d * NN + (k0 + 128) + ld_c8 * 8);
            }
        }
        cp_commit();

        // ---- warp-local softmax: rows g (m0) and g+8 (m1) over 128 cols ----
        float m0 = -3.0e38f, m1 = -3.0e38f;
        #pragma unroll
        for (int nf = 0; nf < 16; nf++) {
            m0 = fmaxf(m0, fmaxf(c1[nf][0], c1[nf][1]));
            m1 = fmaxf(m1, fmaxf(c1[nf][2], c1[nf][3]));
        }
        m0 = fmaxf(m0, __shfl_xor_sync(0xffffffffu, m0, 1));
        m0 = fmaxf(m0, __shfl_xor_sync(0xffffffffu, m0, 2));
        m1 = fmaxf(m1, __shfl_xor_sync(0xffffffffu, m1, 1));
        m1 = fmaxf(m1, __shfl_xor_sync(0xffffffffu, m1, 2));

        float nm0 = fmaxf(m0, lm0);
        float nm1 = fmaxf(m1, lm1);
        float s0 = 0.f, s1 = 0.f;
        unsigned ph[16][2];
        #pragma unroll
        for (int nf = 0; nf < 16; nf++) {
            __half2 ha = __floats2half2_rn((c1[nf][0] - nm0) * CE,
                                           (c1[nf][1] - nm0) * CE);
            __half2 hb = __floats2half2_rn((c1[nf][2] - nm1) * CE,
                                           (c1[nf][3] - nm1) * CE);
            unsigned pa = h2exp2(*(unsigned*)&ha);
            unsigned pc = h2exp2(*(unsigned*)&hb);
            float2 fa = __half22float2(*(__half2*)&pa);
            float2 fc = __half22float2(*(__half2*)&pc);
            s0 += fa.x + fa.y;
            s1 += fc.x + fc.y;
            ph[nf][0] = pa;   // rows g
            ph[nf][1] = pc;   // rows g+8
        }
        s0 += __shfl_xor_sync(0xffffffffu, s0, 1);
        s0 += __shfl_xor_sync(0xffffffffu, s0, 2);
        s1 += __shfl_xor_sync(0xffffffffu, s1, 1);
        s1 += __shfl_xor_sync(0xffffffffu, s1, 2);

        float f0 = exp2f((lm0 - nm0) * CE);
        float f1 = exp2f((lm1 - nm1) * CE);
        ll0 = ll0 * f0 + s0;
        ll1 = ll1 * f1 + s1;
        lm0 = nm0;
        lm1 = nm1;
        #pragma unroll
        for (int nf = 0; nf < 8; nf++) {
            Oa[nf][0] *= f0; Oa[nf][1] *= f0;
            Oa[nf][2] *= f1; Oa[nf][3] *= f1;
        }

        cp_wait<1>();                 // V(it) done (K(it+1) may still fly)
        __syncthreads();              // [B2] Vs visible to all warps

        // ---- GEMM2: O(16q x 64d) += P V^T over full 128 k ----
        #pragma unroll
        for (int ks = 0; ks < 8; ks++) {
            const int koff = ks * 16;
            unsigned bv[8][2];
            #pragma unroll
            for (int j = 0; j < 4; j++) {
                unsigned r4[4];
                ldsm4(r4, vs_u +
                    (unsigned)(((j * 16 + rA) * STR + koff + cA) * 2));
                bv[2 * j][0] = r4[0]; bv[2 * j][1] = r4[1];
                bv[2 * j + 1][0] = r4[2]; bv[2 * j + 1][1] = r4[3];
            }
            unsigned af[4] = { ph[2 * ks][0], ph[2 * ks][1],
                               ph[2 * ks + 1][0], ph[2 * ks + 1][1] };
            #pragma unroll
            for (int nf = 0; nf < 8; nf++)
                mma16h(Oa[nf], af, bv[nf]);
        }
    }

    // ---- epilogue: direct store (warp owns all k) ----
    const size_t base = ((size_t)b * CC + h * DIM) * NN + q0;
    const int q = m1off + g;
    const float inv0 = 1.f / ll0;
    const float inv1 = 1.f / ll1;
    #pragma unroll
    for (int nf = 0; nf < 8; nf++) {
        int col = nf * 8 + 2 * t4;
        size_t a0 = base + (size_t)col * NN + q;
        out[a0]      = x[a0]      + Oa[nf][0] * inv0;
        out[a0 + NN] = x[a0 + NN] + Oa[nf][1] * inv0;
        size_t a2 = a0 + 8;
        out[a2]      = x[a2]      + Oa[nf][2] * inv1;
        out[a2 + NN] = x[a2 + NN] + Oa[nf][3] * inv1;
    }
}

// ---------------------------------------------------------------------------
// Launch
// ---------------------------------------------------------------------------
extern "C" void kernel_launch(void* const* d_in, const int* in_sizes, int n_in,
                              void* d_out, int out_size) {
    const float* x  = (const float*)d_in[0];
    const float* pv = (const float*)d_in[1];
    const float* pg = (const float*)d_in[2];
    const float* pb = (const float*)d_in[3];
    float* out = (float*)d_out;

    convert_x<<<(BB * CC * NN) / (256 * 4), 256>>>(x);
    prep_w<<<O3 / 8, 256>>>(pv, pg);

    cudaFuncSetAttribute(proj_mma,
                         cudaFuncAttributeMaxDynamicSharedMemorySize, PROJ_SMEM);
    dim3 pgrid(NN / 128, O3 / 128, BB);
    proj_mma<<<pgrid, 256, PROJ_SMEM>>>(pb);

    cudaFuncSetAttribute(attn_mma,
                         cudaFuncAttributeMaxDynamicSharedMemorySize, ATTN_SMEM);
    dim3 agrid(NN / 128, BB * HEADS);
    attn_mma<<<agrid, 256, ATTN_SMEM>>>(x, out);
}

// round 17
// speedup vs baseline: 6.8887x; 1.0984x over previous
#include <cuda_runtime.h>
#include <cuda_fp16.h>
#include <math.h>

// Problem constants
#define CC    512      // channels
#define O3    1536     // 3*C
#define NN    1024     // H*W
#define BB    8        // batch
#define DIM   64       // head dim
#define HEADS 8

// ---------------------------------------------------------------------------
// Scratch
// ---------------------------------------------------------------------------
__device__ __half g_wh[(size_t)O3 * CC];              // fp16 weight-normed W
__device__ __half g_xh[(size_t)BB * CC * NN];         // fp16 x
__device__ __half g_qkvh[(size_t)BB * O3 * NN];       // 25 MB fp16 qkv

// ---------------------------------------------------------------------------
// helpers
// ---------------------------------------------------------------------------
__device__ __forceinline__ unsigned smaddr(const void* p) {
    return (unsigned)__cvta_generic_to_shared(p);
}
__device__ __forceinline__ void cpa16(unsigned dst, const void* src) {
    asm volatile("cp.async.cg.shared.global [%0], [%1], 16;" :: "r"(dst), "l"(src));
}
__device__ __forceinline__ void cp_commit() {
    asm volatile("cp.async.commit_group;");
}
template<int N> __device__ __forceinline__ void cp_wait() {
    asm volatile("cp.async.wait_group %0;" :: "n"(N));
}
__device__ __forceinline__ void mma16h(float* c, const unsigned* a, const unsigned* b) {
    asm volatile(
        "mma.sync.aligned.m16n8k16.row.col.f32.f16.f16.f32 "
        "{%0,%1,%2,%3}, {%4,%5,%6,%7}, {%8,%9}, {%0,%1,%2,%3};\n"
        : "+f"(c[0]), "+f"(c[1]), "+f"(c[2]), "+f"(c[3])
        : "r"(a[0]), "r"(a[1]), "r"(a[2]), "r"(a[3]), "r"(b[0]), "r"(b[1]));
}
__device__ __forceinline__ void ldsm4(unsigned* r, unsigned a) {
    asm volatile("ldmatrix.sync.aligned.m8n8.x4.shared.b16 {%0,%1,%2,%3}, [%4];"
        : "=r"(r[0]), "=r"(r[1]), "=r"(r[2]), "=r"(r[3]) : "r"(a));
}
__device__ __forceinline__ void ldsm4t(unsigned* r, unsigned a) {
    asm volatile("ldmatrix.sync.aligned.m8n8.x4.trans.shared.b16 {%0,%1,%2,%3}, [%4];"
        : "=r"(r[0]), "=r"(r[1]), "=r"(r[2]), "=r"(r[3]) : "r"(a));
}
__device__ __forceinline__ unsigned h2exp2(unsigned x) {
    unsigned r;
    asm("ex2.approx.f16x2 %0, %1;" : "=r"(r) : "r"(x));
    return r;
}

// ---------------------------------------------------------------------------
// Kernel 0: x -> fp16
// ---------------------------------------------------------------------------
__global__ void convert_x(const float* __restrict__ x) {
    size_t i = ((size_t)blockIdx.x * 256 + threadIdx.x) * 4;
    float4 v = *(const float4*)(x + i);
    *(__half2*)(g_xh + i)     = __floats2half2_rn(v.x, v.y);
    *(__half2*)(g_xh + i + 2) = __floats2half2_rn(v.z, v.w);
}

// ---------------------------------------------------------------------------
// Kernel 1: w[o][c] = fp16( proj_g[o]/||proj_v[o,:]|| * proj_v[o][c] )
// ---------------------------------------------------------------------------
__global__ void prep_w(const float* __restrict__ pv,
                       const float* __restrict__ pg) {
    int o = blockIdx.x * 8 + (threadIdx.x >> 5);
    int lane = threadIdx.x & 31;
    const float* row = pv + (size_t)o * CC;
    float s = 0.f;
    #pragma unroll 4
    for (int i = lane; i < CC; i += 32) { float v = row[i]; s += v * v; }
    #pragma unroll
    for (int off = 16; off; off >>= 1) s += __shfl_xor_sync(0xffffffffu, s, off);
    float sc = pg[o] / sqrtf(s);
    #pragma unroll 4
    for (int c = lane * 2; c < CC; c += 64)
        *(__half2*)(g_wh + (size_t)o * CC + c) =
            __floats2half2_rn(row[c] * sc, row[c + 1] * sc);
}

// ---------------------------------------------------------------------------
// Kernel 2: qkv = w @ x + b  (fp16 m16n8k16 mma, ldmatrix, 4-stage cp.async).
// Unchanged (control).
// ---------------------------------------------------------------------------
#define PK 32
#define WTS 40
#define XTS 136
#define W_HALFS (128 * WTS)
#define X_HALFS (PK * XTS)
#define STG_B ((W_HALFS + X_HALFS) * 2)
#define NSTG 4
#define PROJ_SMEM (NSTG * STG_B)         // 75,776 B

__global__ __launch_bounds__(256, 2)
void proj_mma(const float* __restrict__ pb) {
    extern __shared__ char psmc[];

    const int b  = blockIdx.z;
    const int bm = blockIdx.y * 128;
    const int bn = blockIdx.x * 128;
    const __half* xb = g_xh + (size_t)b * CC * NN;
    __half* outp = g_qkvh + (size_t)b * O3 * NN;

    const int t    = threadIdx.x;
    const int w    = t >> 5;
    const int lane = t & 31;
    const int g    = lane >> 2;
    const int t4   = lane & 3;
    const int moff = (w & 1) * 64;
    const int noff = (w >> 1) * 32;

    const unsigned base_u = smaddr(psmc);
    const int rA = (lane & 8) + (lane & 7);
    const int cA = (lane & 16) >> 1;
    const int rB = lane & 15;
    const int cB = (lane & 16) >> 1;

    float c[4][4][4];
    #pragma unroll
    for (int mf = 0; mf < 4; mf++)
        #pragma unroll
        for (int nf = 0; nf < 4; nf++)
            #pragma unroll
            for (int i = 0; i < 4; i++) c[mf][nf][i] = 0.f;

    auto load_stage = [&](int stg, int kt) {
        unsigned sd = base_u + stg * STG_B;
        int k0 = kt * PK;
        #pragma unroll
        for (int i = 0; i < 2; i++) {
            int idx = t + i * 256;
            int r = idx >> 2, c8 = idx & 3;
            cpa16(sd + (unsigned)(r * WTS + c8 * 8) * 2,
                  g_wh + (size_t)(bm + r) * CC + k0 + c8 * 8);
        }
        unsigned xd = sd + W_HALFS * 2;
        #pragma unroll
        for (int i = 0; i < 2; i++) {
            int idx = t + i * 256;
            int r = idx >> 4, c8 = idx & 15;
            cpa16(xd + (unsigned)(r * XTS + c8 * 8) * 2,
                  xb + (size_t)(k0 + r) * NN + bn + c8 * 8);
        }
    };

    load_stage(0, 0); cp_commit();
    load_stage(1, 1); cp_commit();
    load_stage(2, 2); cp_commit();

    for (int kt = 0; kt < 16; kt++) {
        cp_wait<2>();
        __syncthreads();
        if (kt + 3 < 16) load_stage((kt + 3) % NSTG, kt + 3);
        cp_commit();

        const unsigned wcur = base_u + (kt % NSTG) * STG_B;
        const unsigned xcur = wcur + W_HALFS * 2;

        #pragma unroll
        for (int ks = 0; ks < 2; ks++) {
            const int koff = ks * 16;
            unsigned a[4][4], bq[4][2];
            #pragma unroll
            for (int mf = 0; mf < 4; mf++)
                ldsm4(a[mf], wcur +
                    (unsigned)(((moff + mf * 16 + rA) * WTS + koff + cA) * 2));
            #pragma unroll
            for (int j = 0; j < 2; j++) {
                unsigned r4[4];
                ldsm4t(r4, xcur +
                    (unsigned)(((koff + rB) * XTS + noff + j * 16 + cB) * 2));
                bq[2 * j][0] = r4[0]; bq[2 * j][1] = r4[1];
                bq[2 * j + 1][0] = r4[2]; bq[2 * j + 1][1] = r4[3];
            }
            #pragma unroll
            for (int mf = 0; mf < 4; mf++)
                #pragma unroll
                for (int nf = 0; nf < 4; nf++)
                    mma16h(c[mf][nf], a[mf], bq[nf]);
        }
    }

    #pragma unroll
    for (int mf = 0; mf < 4; mf++) {
        int o = bm + moff + mf * 16 + g;
        float bias0 = pb[o], bias1 = pb[o + 8];
        #pragma unroll
        for (int nf = 0; nf < 4; nf++) {
            int n = bn + noff + nf * 8 + 2 * t4;
            *(__half2*)(outp + (size_t)o * NN + n) =
                __floats2half2_rn(c[mf][nf][0] + bias0, c[mf][nf][1] + bias0);
            *(__half2*)(outp + (size_t)(o + 8) * NN + n) =
                __floats2half2_rn(c[mf][nf][2] + bias1, c[mf][nf][3] + bias1);
        }
    }
}

// ---------------------------------------------------------------------------
// Kernel 3: flash attention, q_w=32 per warp, 64-wide k chunks, occ 2.
// CTA = 128 threads / 4 warps; each warp owns 32 q-rows x full k.
// SMEM B-reads per mma halved vs q_w=16; 2 CTAs/SM restore cross-CTA overlap.
// K chunks double-buffered; V single-buffered (issued at iter top).
// Chunk tiles stride 72 halves (144B == 4 words mod 32 banks -> ldmatrix CF).
// ---------------------------------------------------------------------------
#define QSTR 136         // Q tile stride (halves)
#define CSTR 72          // K/V chunk stride (halves)
#define KCH_B 9216       // 64*72*2 bytes per K chunk buffer
#define QS_OFF   0       // 64*136*2 = 17408
#define KS_OFF   17408   // 2 chunks -> 18432
#define VS_OFF   35840   // 9216
#define ATTN_SMEM 45056

__global__ __launch_bounds__(128, 2)
void attn_mma(const float* __restrict__ x, float* __restrict__ out) {
    extern __shared__ char smc[];

    const int t    = threadIdx.x;
    const int w    = t >> 5;           // 0..3
    const int lane = t & 31;
    const int g    = lane >> 2;
    const int t4   = lane & 3;
    const int bh   = blockIdx.y;
    const int b    = bh >> 3, h = bh & 7;
    const int q0   = blockIdx.x * 128;

    const int m1off = w * 32;          // warp's 32-row q-stripe

    const __half* Qg = g_qkvh + ((size_t)b * O3 + h * DIM) * NN;
    const __half* Kg = Qg + (size_t)CC * NN;
    const __half* Vg = Qg + (size_t)2 * CC * NN;

    const unsigned qs_u = smaddr(smc + QS_OFF);
    const unsigned ks_u = smaddr(smc + KS_OFF);
    const unsigned vs_u = smaddr(smc + VS_OFF);

    // ldmatrix per-lane address components
    const int rA = ((lane & 16) >> 1) + (lane & 7);  // x4 rows (A-style / V-B)
    const int cA = lane & 8;                         // x4 col offset (halves)
    const int rB = lane & 15;                        // x4t rows
    const int cB = (lane & 16) >> 1;                 // x4t col offset

    const int ldq_d  = t >> 4;         // Q loader: 8 d-rows/iter
    const int ldq_c8 = t & 15;         // 16 x 8 halves = 128 q cols
    const int ldk_d  = t >> 3;         // K/V chunk loader: 16 d-rows/iter
    const int ldk_c8 = t & 7;          // 8 x 8 halves = 64 k cols

    // Prologue: async Q tile + K chunk 0
    #pragma unroll
    for (int i = 0; i < 8; i++) {
        int d = ldq_d + i * 8;
        cpa16(qs_u + (unsigned)(d * QSTR + ldq_c8 * 8) * 2,
              Qg + (size_t)d * NN + q0 + ldq_c8 * 8);
    }
    #pragma unroll
    for (int i = 0; i < 4; i++) {
        int d = ldk_d + i * 16;
        cpa16(ks_u + (unsigned)(d * CSTR + ldk_c8 * 8) * 2,
              Kg + (size_t)d * NN + 0 + ldk_c8 * 8);
    }
    cp_commit();
    cp_wait<0>();
    __syncthreads();

    // Preload warp's Q A-fragments: 2 m16 tiles x 4 k16 chunks (32 regs)
    unsigned qf[2][4][4];
    #pragma unroll
    for (int mf = 0; mf < 2; mf++)
        #pragma unroll
        for (int ks = 0; ks < 4; ks++)
            ldsm4t(qf[mf][ks], qs_u +
                (unsigned)(((ks * 16 + rA) * QSTR + m1off + mf * 16 + cA) * 2));

    float Oa[2][8][4];
    #pragma unroll
    for (int mf = 0; mf < 2; mf++)
        #pragma unroll
        for (int nf = 0; nf < 8; nf++)
            #pragma unroll
            for (int i = 0; i < 4; i++) Oa[mf][nf][i] = 0.f;

    float lm[2][2], ll[2][2];
    #pragma unroll
    for (int mf = 0; mf < 2; mf++) {
        lm[mf][0] = lm[mf][1] = -3.0e38f;
        ll[mf][0] = ll[mf][1] = 0.f;
    }

    const float CE = 0.18033688f;   // 0.125 * log2(e)

    for (int it = 0; it < 16; it++) {
        const int k0 = it * 64;
        if (it) {
            cp_wait<0>();
            __syncthreads();          // [B1] K(it) visible; Vs free
        }

        // issue V chunk (it)
        #pragma unroll
        for (int i = 0; i < 4; i++) {
            int d = ldk_d + i * 16;
            cpa16(vs_u + (unsigned)(d * CSTR + ldk_c8 * 8) * 2,
                  Vg + (size_t)d * NN + k0 + ldk_c8 * 8);
        }
        cp_commit();

        const unsigned ks_cur = ks_u + (unsigned)(it & 1) * KCH_B;

        // ---- GEMM1: S(32q x 64k) = Q^T K ----
        float c1[2][8][4];
        #pragma unroll
        for (int mf = 0; mf < 2; mf++)
            #pragma unroll
            for (int nf = 0; nf < 8; nf++)
                #pragma unroll
                for (int i = 0; i < 4; i++) c1[mf][nf][i] = 0.f;

        #pragma unroll
        for (int ks = 0; ks < 4; ks++) {
            const int koff = ks * 16;
            unsigned bq[8][2];
            #pragma unroll
            for (int j = 0; j < 4; j++) {
                unsigned r4[4];
                ldsm4t(r4, ks_cur +
                    (unsigned)(((koff + rB) * CSTR + j * 16 + cB) * 2));
                bq[2 * j][0] = r4[0]; bq[2 * j][1] = r4[1];
                bq[2 * j + 1][0] = r4[2]; bq[2 * j + 1][1] = r4[3];
            }
            #pragma unroll
            for (int mf = 0; mf < 2; mf++)
                #pragma unroll
                for (int nf = 0; nf < 8; nf++)
                    mma16h(c1[mf][nf], qf[mf][ks], bq[nf]);
        }

        // prefetch K chunk (it+1)
        if (it < 15) {
            const unsigned ks_nxt = ks_u + (unsigned)((it + 1) & 1) * KCH_B;
            #pragma unroll
            for (int i = 0; i < 4; i++) {
                int d = ldk_d + i * 16;
                cpa16(ks_nxt + (unsigned)(d * CSTR + ldk_c8 * 8) * 2,
                      Kg + (size_t)d * NN + (k0 + 64) + ldk_c8 * 8);
            }
        }
        cp_commit();

        // ---- warp-local online softmax over this 64-col chunk ----
        unsigned ph[2][8][2];
        #pragma unroll
        for (int mf = 0; mf < 2; mf++) {
            float m0 = -3.0e38f, m1 = -3.0e38f;
            #pragma unroll
            for (int nf = 0; nf < 8; nf++) {
                m0 = fmaxf(m0, fmaxf(c1[mf][nf][0], c1[mf][nf][1]));
                m1 = fmaxf(m1, fmaxf(c1[mf][nf][2], c1[mf][nf][3]));
            }
            m0 = fmaxf(m0, __shfl_xor_sync(0xffffffffu, m0, 1));
            m0 = fmaxf(m0, __shfl_xor_sync(0xffffffffu, m0, 2));
            m1 = fmaxf(m1, __shfl_xor_sync(0xffffffffu, m1, 1));
            m1 = fmaxf(m1, __shfl_xor_sync(0xffffffffu, m1, 2));

            float nm0 = fmaxf(m0, lm[mf][0]);
            float nm1 = fmaxf(m1, lm[mf][1]);
            float s0 = 0.f, s1 = 0.f;
            #pragma unroll
            for (int nf = 0; nf < 8; nf++) {
                __half2 ha = __floats2half2_rn((c1[mf][nf][0] - nm0) * CE,
                                               (c1[mf][nf][1] - nm0) * CE);
                __half2 hb = __floats2half2_rn((c1[mf][nf][2] - nm1) * CE,
                                               (c1[mf][nf][3] - nm1) * CE);
                unsigned pa = h2exp2(*(unsigned*)&ha);
                unsigned pc = h2exp2(*(unsigned*)&hb);
                float2 fa = __half22float2(*(__half2*)&pa);
                float2 fc = __half22float2(*(__half2*)&pc);
                s0 += fa.x + fa.y;
                s1 += fc.x + fc.y;
                ph[mf][nf][0] = pa;   // rows g
                ph[mf][nf][1] = pc;   // rows g+8
            }
            s0 += __shfl_xor_sync(0xffffffffu, s0, 1);
            s0 += __shfl_xor_sync(0xffffffffu, s0, 2);
            s1 += __shfl_xor_sync(0xffffffffu, s1, 1);
            s1 += __shfl_xor_sync(0xffffffffu, s1, 2);

            float f0 = exp2f((lm[mf][0] - nm0) * CE);
            float f1 = exp2f((lm[mf][1] - nm1) * CE);
            ll[mf][0] = ll[mf][0] * f0 + s0;
            ll[mf][1] = ll[mf][1] * f1 + s1;
            lm[mf][0] = nm0;
            lm[mf][1] = nm1;
            #pragma unroll
            for (int nf = 0; nf < 8; nf++) {
                Oa[mf][nf][0] *= f0; Oa[mf][nf][1] *= f0;
                Oa[mf][nf][2] *= f1; Oa[mf][nf][3] *= f1;
            }
        }

        cp_wait<1>();                 // V(it) done (K(it+1) may still fly)
        __syncthreads();              // [B2] Vs visible

        // ---- GEMM2: O(32q x 64d) += P V^T over 64-k chunk ----
        #pragma unroll
        for (int ks2 = 0; ks2 < 4; ks2++) {
            const int koff = ks2 * 16;
            unsigned bv[8][2];
            #pragma unroll
            for (int j = 0; j < 4; j++) {
                unsigned r4[4];
                ldsm4(r4, vs_u +
                    (unsigned)(((j * 16 + rA) * CSTR + koff + cA) * 2));
                bv[2 * j][0] = r4[0]; bv[2 * j][1] = r4[1];
                bv[2 * j + 1][0] = r4[2]; bv[2 * j + 1][1] = r4[3];
            }
            #pragma unroll
            for (int mf = 0; mf < 2; mf++) {
                unsigned af[4] = { ph[mf][2 * ks2][0], ph[mf][2 * ks2][1],
                                   ph[mf][2 * ks2 + 1][0], ph[mf][2 * ks2 + 1][1] };
                #pragma unroll
                for (int nf = 0; nf < 8; nf++)
                    mma16h(Oa[mf][nf], af, bv[nf]);
            }
        }
    }

    // ---- epilogue: direct store (warp owns all k) ----
    const size_t base = ((size_t)b * CC + h * DIM) * NN + q0;
    #pragma unroll
    for (int mf = 0; mf < 2; mf++) {
        const int q = m1off + mf * 16 + g;
        const float inv0 = 1.f / ll[mf][0];
        const float inv1 = 1.f / ll[mf][1];
        #pragma unroll
        for (int nf = 0; nf < 8; nf++) {
            int col = nf * 8 + 2 * t4;
            size_t a0 = base + (size_t)col * NN + q;
            out[a0]      = x[a0]      + Oa[mf][nf][0] * inv0;
            out[a0 + NN] = x[a0 + NN] + Oa[mf][nf][1] * inv0;
            size_t a2 = a0 + 8;
            out[a2]      = x[a2]      + Oa[mf][nf][2] * inv1;
            out[a2 + NN] = x[a2 + NN] + Oa[mf][nf][3] * inv1;
        }
    }
}

// ---------------------------------------------------------------------------
// Launch
// ---------------------------------------------------------------------------
extern "C" void kernel_launch(void* const* d_in, const int* in_sizes, int n_in,
                              void* d_out, int out_size) {
    const float* x  = (const float*)d_in[0];
    const float* pv = (const float*)d_in[1];
    const float* pg = (const float*)d_in[2];
    const float* pb = (const float*)d_in[3];
    float* out = (float*)d_out;

    convert_x<<<(BB * CC * NN) / (256 * 4), 256>>>(x);
    prep_w<<<O3 / 8, 256>>>(pv, pg);

    cudaFuncSetAttribute(proj_mma,
                         cudaFuncAttributeMaxDynamicSharedMemorySize, PROJ_SMEM);
    dim3 pgrid(NN / 128, O3 / 128, BB);
    proj_mma<<<pgrid, 256, PROJ_SMEM>>>(pb);

    cudaFuncSetAttribute(attn_mma,
                         cudaFuncAttributeMaxDynamicSharedMemorySize, ATTN_SMEM);
    dim3 agrid(NN / 128, BB * HEADS);
    attn_mma<<<agrid, 128, ATTN_SMEM>>>(x, out);
}